// round 12
// baseline (speedup 1.0000x reference)
#include <cuda_runtime.h>
#include <cuda_bf16.h>
#include <math.h>
#include <stdint.h>

#define BATCH 4
#define HI 128
#define WI 128
#define HO 64
#define WO 64
#define DIM 128
#define NPIX_IN  (HI*WI)
#define NPIX_OUT (HO*WO)
#define NROWS_IN  (BATCH*NPIX_IN)   // 65536
#define NROWS_OUT (BATCH*NPIX_OUT)  // 16384

// ---------------- scratch (device globals) ----------------------------------
__device__ float g_k   [(size_t)NROWS_IN*DIM];
__device__ float g_v   [(size_t)NROWS_IN*DIM];
__device__ float g_q   [(size_t)NROWS_OUT*DIM];
__device__ float g_xout[(size_t)NROWS_OUT*DIM];
__device__ float g_colsum[BATCH*NPIX_OUT];

// bf16 split buffers (hi/lo)
__device__ __align__(16) __nv_bfloat16 g_x_h  [(size_t)NROWS_IN*DIM];
__device__ __align__(16) __nv_bfloat16 g_x_l  [(size_t)NROWS_IN*DIM];
__device__ __align__(16) __nv_bfloat16 g_xli_h[(size_t)NROWS_IN*DIM];   // LN_in(x)
__device__ __align__(16) __nv_bfloat16 g_xli_l[(size_t)NROWS_IN*DIM];
__device__ __align__(16) __nv_bfloat16 g_xo_h [(size_t)NROWS_OUT*DIM];  // xout (post-upd)
__device__ __align__(16) __nv_bfloat16 g_xo_l [(size_t)NROWS_OUT*DIM];
__device__ __align__(16) __nv_bfloat16 g_xq_h [(size_t)NROWS_OUT*DIM];  // LN(xout)
__device__ __align__(16) __nv_bfloat16 g_xq_l [(size_t)NROWS_OUT*DIM];
__device__ __align__(16) __nv_bfloat16 g_hh_h [(size_t)NROWS_OUT*2*DIM];
__device__ __align__(16) __nv_bfloat16 g_hh_l [(size_t)NROWS_OUT*2*DIM];
// transposed-split weights [N,K]
__device__ __align__(16) __nv_bfloat16 g_wq_h[DIM*DIM], g_wq_l[DIM*DIM];
__device__ __align__(16) __nv_bfloat16 g_wk_h[DIM*DIM], g_wk_l[DIM*DIM];
__device__ __align__(16) __nv_bfloat16 g_wv_h[DIM*DIM], g_wv_l[DIM*DIM];
__device__ __align__(16) __nv_bfloat16 g_w1_h[2*DIM*DIM], g_w1_l[2*DIM*DIM]; // [256,128]
__device__ __align__(16) __nv_bfloat16 g_w2_h[2*DIM*DIM], g_w2_l[2*DIM*DIM]; // [128,256]
// conv weights per tap: [tap][o][i] bf16 split
__device__ __align__(16) __nv_bfloat16 g_cw_h[9*DIM*DIM], g_cw_l[9*DIM*DIM];

// ---------------- helpers ----------------------------------------------------
static __device__ __forceinline__ float wredsum(float v){
#pragma unroll
    for (int o = 16; o > 0; o >>= 1) v += __shfl_xor_sync(0xffffffffu, v, o);
    return v;
}
static __device__ __forceinline__ float geluf(float x){
    return 0.5f * x * (1.0f + erff(x * 0.70710678118654752440f));
}
static __device__ __forceinline__ uint32_t smem_u32(const void* p){
    uint32_t a;
    asm("{ .reg .u64 t; cvta.to.shared.u64 t, %1; cvt.u32.u64 %0, t; }" : "=r"(a) : "l"(p));
    return a;
}
static __device__ __forceinline__ void split2(float v, __nv_bfloat16& h, __nv_bfloat16& l){
    h = __float2bfloat16(v);
    l = __float2bfloat16(v - __bfloat162float(h));
}
static __device__ __forceinline__ void split_store4(
    __nv_bfloat16* ph, __nv_bfloat16* pl, const float* v)
{
    __nv_bfloat16 h[4], l[4];
#pragma unroll
    for (int i = 0; i < 4; i++) split2(v[i], h[i], l[i]);
    *reinterpret_cast<uint2*>(ph) = *reinterpret_cast<const uint2*>(h);
    *reinterpret_cast<uint2*>(pl) = *reinterpret_cast<const uint2*>(l);
}

// ---------------- mma primitives (baseline PTX: sm_80-compatible) -----------
static __device__ __forceinline__ void ldsm_x4(uint32_t* r, uint32_t addr){
    asm volatile("ldmatrix.sync.aligned.m8n8.x4.shared.b16 {%0,%1,%2,%3}, [%4];"
        : "=r"(r[0]), "=r"(r[1]), "=r"(r[2]), "=r"(r[3]) : "r"(addr));
}
static __device__ __forceinline__ void mma16816(
    float* c, const uint32_t* a, uint32_t b0, uint32_t b1)
{
    asm volatile(
        "mma.sync.aligned.m16n8k16.row.col.f32.bf16.bf16.f32 "
        "{%0,%1,%2,%3}, {%4,%5,%6,%7}, {%8,%9}, {%0,%1,%2,%3};"
        : "+f"(c[0]), "+f"(c[1]), "+f"(c[2]), "+f"(c[3])
        : "r"(a[0]), "r"(a[1]), "r"(a[2]), "r"(a[3]), "r"(b0), "r"(b1));
}

#define EPI_STORE 0
#define EPI_GELU  1
#define EPI_LNRES 2

#define TSTRIDE 72                      // bf16 elements per smem row (pad 64->72)
#define TBYTES  (128*TSTRIDE*2)         // 18432 bytes per tile
#define OFF_AH  0
#define OFF_AL  (TBYTES)
#define OFF_BH  (2*TBYTES)
#define OFF_BL  (3*TBYTES)
#define SMEM_MMA (4*TBYTES)             // 73728

// ---------------- bf16-3x tensor-core GEMM -----------------------------------
// D[128 tile, 128 tile] = A @ B^T; A[M,Ktot] hi/lo, B[N,Ktot] hi/lo (row-major).
__global__ void __launch_bounds__(256) gemm_mma(
    const __nv_bfloat16* __restrict__ Ah, const __nv_bfloat16* __restrict__ Al, int Ktot,
    const __nv_bfloat16* __restrict__ Bh, const __nv_bfloat16* __restrict__ Bl,
    const float* __restrict__ bias,
    const float* __restrict__ lng, const float* __restrict__ lnb,
    float* __restrict__ C, int ldc,
    float* __restrict__ res, float* __restrict__ fin,
    __nv_bfloat16* __restrict__ ohi, __nv_bfloat16* __restrict__ olo, int ldo,
    int epi, int writeFinal)
{
    extern __shared__ char sm[];
    const uint32_t smb = smem_u32(sm);
    const int tid = threadIdx.x, wid = tid >> 5, lane = tid & 31;
    const int wm = wid & 3, wn = wid >> 2;
    const int mBase = blockIdx.x * 128;
    const int col0  = blockIdx.y * 128;

    float acc[2][8][4];
#pragma unroll
    for (int mt = 0; mt < 2; mt++)
#pragma unroll
        for (int nt = 0; nt < 8; nt++)
#pragma unroll
            for (int i = 0; i < 4; i++) acc[mt][nt][i] = 0.f;

    const __nv_bfloat16* Ah0 = Ah + (size_t)mBase*Ktot;
    const __nv_bfloat16* Al0 = Al + (size_t)mBase*Ktot;
    const __nv_bfloat16* Bh0 = Bh + (size_t)col0*Ktot;
    const __nv_bfloat16* Bl0 = Bl + (size_t)col0*Ktot;

    const int aRow = lane & 15, aKh = (lane >> 4) << 3;
    const int bRow = (lane & 7) + ((lane >> 4) << 3);
    const int bKh  = ((lane >> 3) & 1) << 3;

    for (int kc = 0; kc < Ktot; kc += 64){
        __syncthreads();
#pragma unroll
        for (int i = 0; i < 4; i++){
            int u = tid + i*256;
            int m = u >> 3, c8 = (u & 7) << 3;
            size_t go = (size_t)m*Ktot + kc + c8;
            int so = (m*TSTRIDE + c8) << 1;
            *reinterpret_cast<uint4*>(sm + OFF_AH + so) = *reinterpret_cast<const uint4*>(Ah0 + go);
            *reinterpret_cast<uint4*>(sm + OFF_AL + so) = *reinterpret_cast<const uint4*>(Al0 + go);
            *reinterpret_cast<uint4*>(sm + OFF_BH + so) = *reinterpret_cast<const uint4*>(Bh0 + go);
            *reinterpret_cast<uint4*>(sm + OFF_BL + so) = *reinterpret_cast<const uint4*>(Bl0 + go);
        }
        __syncthreads();

#pragma unroll
        for (int ks = 0; ks < 4; ks++){
            uint32_t ah[2][4], al[2][4];
#pragma unroll
            for (int mt = 0; mt < 2; mt++){
                const int eoff = ((wm*32 + mt*16 + aRow)*TSTRIDE + ks*16 + aKh) << 1;
                ldsm_x4(ah[mt], smb + OFF_AH + eoff);
                ldsm_x4(al[mt], smb + OFF_AL + eoff);
            }
#pragma unroll
            for (int np = 0; np < 4; np++){
                const int eoff = ((wn*64 + np*16 + bRow)*TSTRIDE + ks*16 + bKh) << 1;
                uint32_t bh4[4], bl4[4];
                ldsm_x4(bh4, smb + OFF_BH + eoff);
                ldsm_x4(bl4, smb + OFF_BL + eoff);
#pragma unroll
                for (int mt = 0; mt < 2; mt++){
#pragma unroll
                    for (int hf = 0; hf < 2; hf++){
                        float* c = acc[mt][np*2 + hf];
                        mma16816(c, ah[mt], bh4[hf*2], bh4[hf*2+1]);
                        mma16816(c, al[mt], bh4[hf*2], bh4[hf*2+1]);
                        mma16816(c, ah[mt], bl4[hf*2], bl4[hf*2+1]);
                    }
                }
            }
        }
    }

    // ---------------- epilogues ----------------
    if (epi == EPI_STORE){
#pragma unroll
        for (int mt = 0; mt < 2; mt++){
            const int row = mBase + wm*32 + mt*16 + (lane >> 2);
#pragma unroll
            for (int nt = 0; nt < 8; nt++){
                const int colg = col0 + wn*64 + nt*8 + ((lane & 3) << 1);
                *reinterpret_cast<float2*>(C + (size_t)row*ldc + colg) =
                    make_float2(acc[mt][nt][0], acc[mt][nt][1]);
                *reinterpret_cast<float2*>(C + (size_t)(row+8)*ldc + colg) =
                    make_float2(acc[mt][nt][2], acc[mt][nt][3]);
            }
        }
    } else if (epi == EPI_GELU){
#pragma unroll
        for (int mt = 0; mt < 2; mt++){
            const int row = mBase + wm*32 + mt*16 + (lane >> 2);
#pragma unroll
            for (int nt = 0; nt < 8; nt++){
                const int colg = col0 + wn*64 + nt*8 + ((lane & 3) << 1);
                const float b0 = bias[colg], b1 = bias[colg+1];
                float v0 = geluf(acc[mt][nt][0] + b0);
                float v1 = geluf(acc[mt][nt][1] + b1);
                float v2 = geluf(acc[mt][nt][2] + b0);
                float v3 = geluf(acc[mt][nt][3] + b1);
                __nv_bfloat16 h0,l0,h1,l1;
                split2(v0,h0,l0); split2(v1,h1,l1);
                *reinterpret_cast<__nv_bfloat162*>(ohi + (size_t)row*ldo + colg) = {h0,h1};
                *reinterpret_cast<__nv_bfloat162*>(olo + (size_t)row*ldo + colg) = {l0,l1};
                split2(v2,h0,l0); split2(v3,h1,l1);
                *reinterpret_cast<__nv_bfloat162*>(ohi + (size_t)(row+8)*ldo + colg) = {h0,h1};
                *reinterpret_cast<__nv_bfloat162*>(olo + (size_t)(row+8)*ldo + colg) = {l0,l1};
            }
        }
    } else { // EPI_LNRES
        __syncthreads();
        float* sf = reinterpret_cast<float*>(sm);
#pragma unroll
        for (int mt = 0; mt < 2; mt++){
            const int lr = wm*32 + mt*16 + (lane >> 2);
#pragma unroll
            for (int nt = 0; nt < 8; nt++){
                const int lc = wn*64 + nt*8 + ((lane & 3) << 1);
                const float b0 = bias[lc], b1 = bias[lc+1];
                sf[lr*132 + lc]       = acc[mt][nt][0] + b0;
                sf[lr*132 + lc + 1]   = acc[mt][nt][1] + b1;
                sf[(lr+8)*132 + lc]   = acc[mt][nt][2] + b0;
                sf[(lr+8)*132 + lc+1] = acc[mt][nt][3] + b1;
            }
        }
        __syncthreads();
        const float4 gg = reinterpret_cast<const float4*>(lng)[lane];
        const float4 lb = reinterpret_cast<const float4*>(lnb)[lane];
        for (int r = wid*16; r < wid*16 + 16; r++){
            float4 v = *reinterpret_cast<float4*>(sf + r*132 + lane*4);
            float mu = wredsum(v.x+v.y+v.z+v.w) * (1.0f/128.0f);
            float dx=v.x-mu, dy=v.y-mu, dz=v.z-mu, dw=v.w-mu;
            float var = wredsum(dx*dx+dy*dy+dz*dz+dw*dw) * (1.0f/128.0f);
            float rs = rsqrtf(var + 1e-5f);
            const int row = mBase + r;
            float* rp = res + (size_t)row*DIM;
            float4 r4 = reinterpret_cast<float4*>(rp)[lane];
            float o[4];
            o[0] = r4.x + dx*rs*gg.x + lb.x;
            o[1] = r4.y + dy*rs*gg.y + lb.y;
            o[2] = r4.z + dz*rs*gg.z + lb.z;
            o[3] = r4.w + dw*rs*gg.w + lb.w;
            float4 o4 = make_float4(o[0],o[1],o[2],o[3]);
            reinterpret_cast<float4*>(rp)[lane] = o4;
            if (writeFinal)
                reinterpret_cast<float4*>(fin + (size_t)row*DIM)[lane] = o4;
            float mu2 = wredsum(o[0]+o[1]+o[2]+o[3]) * (1.0f/128.0f);
            float e0=o[0]-mu2, e1=o[1]-mu2, e2=o[2]-mu2, e3=o[3]-mu2;
            float var2 = wredsum(e0*e0+e1*e1+e2*e2+e3*e3) * (1.0f/128.0f);
            float rs2 = rsqrtf(var2 + 1e-5f);
            float x2[4];
            x2[0] = e0*rs2*gg.x + lb.x; x2[1] = e1*rs2*gg.y + lb.y;
            x2[2] = e2*rs2*gg.z + lb.z; x2[3] = e3*rs2*gg.w + lb.w;
            split_store4(ohi + (size_t)row*DIM + lane*4,
                         olo + (size_t)row*DIM + lane*4, x2);
        }
    }
}

// ---------------- conv as implicit tensor-core GEMM --------------------------
__global__ void __launch_bounds__(256) conv_mma(
    const float* __restrict__ lng, const float* __restrict__ lnb)
{
    extern __shared__ char sm[];
    const uint32_t smb = smem_u32(sm);
    const int tid = threadIdx.x, wid = tid >> 5, lane = tid & 31;
    const int wm = wid & 3, wn = wid >> 2;
    const int mBase = blockIdx.x * 128;

    float acc[2][8][4];
#pragma unroll
    for (int mt = 0; mt < 2; mt++)
#pragma unroll
        for (int nt = 0; nt < 8; nt++)
#pragma unroll
            for (int i = 0; i < 4; i++) acc[mt][nt][i] = 0.f;

    const int aRow = lane & 15, aKh = (lane >> 4) << 3;
    const int bRow = (lane & 7) + ((lane >> 4) << 3);
    const int bKh  = ((lane >> 3) & 1) << 3;

    for (int tap = 0; tap < 9; tap++){
        const int kh = tap/3 - 1, kw = tap%3 - 1;
        for (int kc = 0; kc < 2; kc++){
            __syncthreads();
#pragma unroll
            for (int i = 0; i < 4; i++){
                int u = tid + i*256;
                int m = u >> 3, c8 = (u & 7) << 3;
                const int p = mBase + m;
                const int b = p >> 12, hw = p & 4095;
                const int h = hw >> 6, w = hw & 63;
                const int hi = 2*h + kh, wi = 2*w + kw;
                uint4 vh = make_uint4(0,0,0,0), vl = make_uint4(0,0,0,0);
                if ((unsigned)hi < HI && (unsigned)wi < WI){
                    size_t go = ((size_t)b*NPIX_IN + hi*WI + wi)*DIM + kc*64 + c8;
                    vh = *reinterpret_cast<const uint4*>(g_x_h + go);
                    vl = *reinterpret_cast<const uint4*>(g_x_l + go);
                }
                int so = (m*TSTRIDE + c8) << 1;
                *reinterpret_cast<uint4*>(sm + OFF_AH + so) = vh;
                *reinterpret_cast<uint4*>(sm + OFF_AL + so) = vl;
                size_t gb = (size_t)tap*DIM*DIM + (size_t)m*DIM + kc*64 + c8;
                *reinterpret_cast<uint4*>(sm + OFF_BH + so) =
                    *reinterpret_cast<const uint4*>(g_cw_h + gb);
                *reinterpret_cast<uint4*>(sm + OFF_BL + so) =
                    *reinterpret_cast<const uint4*>(g_cw_l + gb);
            }
            __syncthreads();
#pragma unroll
            for (int ks = 0; ks < 4; ks++){
                uint32_t ah[2][4], al[2][4];
#pragma unroll
                for (int mt = 0; mt < 2; mt++){
                    const int eoff = ((wm*32 + mt*16 + aRow)*TSTRIDE + ks*16 + aKh) << 1;
                    ldsm_x4(ah[mt], smb + OFF_AH + eoff);
                    ldsm_x4(al[mt], smb + OFF_AL + eoff);
                }
#pragma unroll
                for (int np = 0; np < 4; np++){
                    const int eoff = ((wn*64 + np*16 + bRow)*TSTRIDE + ks*16 + bKh) << 1;
                    uint32_t bh4[4], bl4[4];
                    ldsm_x4(bh4, smb + OFF_BH + eoff);
                    ldsm_x4(bl4, smb + OFF_BL + eoff);
#pragma unroll
                    for (int mt = 0; mt < 2; mt++){
#pragma unroll
                        for (int hf = 0; hf < 2; hf++){
                            float* c = acc[mt][np*2 + hf];
                            mma16816(c, ah[mt], bh4[hf*2], bh4[hf*2+1]);
                            mma16816(c, al[mt], bh4[hf*2], bh4[hf*2+1]);
                            mma16816(c, ah[mt], bl4[hf*2], bl4[hf*2+1]);
                        }
                    }
                }
            }
        }
    }

    __syncthreads();
    float* sf = reinterpret_cast<float*>(sm);
#pragma unroll
    for (int mt = 0; mt < 2; mt++){
        const int lr = wm*32 + mt*16 + (lane >> 2);
#pragma unroll
        for (int nt = 0; nt < 8; nt++){
            const int lc = wn*64 + nt*8 + ((lane & 3) << 1);
            sf[lr*132 + lc]       = acc[mt][nt][0];
            sf[lr*132 + lc + 1]   = acc[mt][nt][1];
            sf[(lr+8)*132 + lc]   = acc[mt][nt][2];
            sf[(lr+8)*132 + lc+1] = acc[mt][nt][3];
        }
    }
    __syncthreads();
    const float4 gg = reinterpret_cast<const float4*>(lng)[lane];
    const float4 lb = reinterpret_cast<const float4*>(lnb)[lane];
    for (int r = wid*16; r < wid*16 + 16; r++){
        float4 v = *reinterpret_cast<float4*>(sf + r*132 + lane*4);
        float mu = wredsum(v.x+v.y+v.z+v.w) * (1.0f/128.0f);
        float dx=v.x-mu, dy=v.y-mu, dz=v.z-mu, dw=v.w-mu;
        float var = wredsum(dx*dx+dy*dy+dz*dz+dw*dw) * (1.0f/128.0f);
        float rs = rsqrtf(var + 1e-5f);
        const int row = mBase + r;
        float o[4];
        o[0] = dx*rs*gg.x + lb.x; o[1] = dy*rs*gg.y + lb.y;
        o[2] = dz*rs*gg.z + lb.z; o[3] = dw*rs*gg.w + lb.w;
        reinterpret_cast<float4*>(g_xout + (size_t)row*DIM)[lane] =
            make_float4(o[0],o[1],o[2],o[3]);
        float mu2 = wredsum(o[0]+o[1]+o[2]+o[3]) * (1.0f/128.0f);
        float e0=o[0]-mu2, e1=o[1]-mu2, e2=o[2]-mu2, e3=o[3]-mu2;
        float var2 = wredsum(e0*e0+e1*e1+e2*e2+e3*e3) * (1.0f/128.0f);
        float rs2 = rsqrtf(var2 + 1e-5f);
        float x2[4];
        x2[0] = e0*rs2*gg.x + lb.x; x2[1] = e1*rs2*gg.y + lb.y;
        x2[2] = e2*rs2*gg.z + lb.z; x2[3] = e3*rs2*gg.w + lb.w;
        split_store4(g_xq_h + (size_t)row*DIM + lane*4,
                     g_xq_l + (size_t)row*DIM + lane*4, x2);
    }
}

// ---------------- conv weight split: [o][i][tap] -> [tap][o][i] hi/lo --------
__global__ void conv_split_kernel(const float* __restrict__ cw){
    int idx = blockIdx.x*256 + threadIdx.x;
    if (idx >= 9*DIM*DIM) return;
    int o   = idx / (DIM*9);
    int rem = idx - o*(DIM*9);
    int i   = rem / 9;
    int tap = rem - i*9;
    __nv_bfloat16 h, l;
    split2(cw[idx], h, l);
    g_cw_h[(size_t)tap*DIM*DIM + o*DIM + i] = h;
    g_cw_l[(size_t)tap*DIM*DIM + o*DIM + i] = l;
}

// ---------------- weight transpose + split: in[K,N] -> out[N,K] hi/lo --------
__global__ void tsplit_kernel(const float* __restrict__ in,
                              __nv_bfloat16* __restrict__ oh,
                              __nv_bfloat16* __restrict__ ol,
                              int K, int N)
{
    int idx = blockIdx.x*256 + threadIdx.x;
    if (idx >= K*N) return;
    int k = idx / N, n = idx - k*N;
    __nv_bfloat16 h, l;
    split2(in[idx], h, l);
    oh[(size_t)n*K + k] = h;
    ol[(size_t)n*K + k] = l;
}

// ---------------- row split (optional LN): fp32 -> bf16 hi/lo ----------------
template<bool DO_LN>
__global__ void __launch_bounds__(256) split_kernel(
    const float* __restrict__ in,
    __nv_bfloat16* __restrict__ oh, __nv_bfloat16* __restrict__ ol,
    const float* __restrict__ g, const float* __restrict__ b)
{
    const int lane = threadIdx.x & 31, warp = threadIdx.x >> 5;
    const size_t row = (size_t)blockIdx.x*8 + warp;
    float4 v = reinterpret_cast<const float4*>(in + row*DIM)[lane];
    if (DO_LN){
        float mu = wredsum(v.x+v.y+v.z+v.w) * (1.0f/DIM);
        float dx=v.x-mu, dy=v.y-mu, dz=v.z-mu, dw=v.w-mu;
        float var = wredsum(dx*dx+dy*dy+dz*dz+dw*dw) * (1.0f/DIM);
        float rs = rsqrtf(var + 1e-5f);
        float4 gg = reinterpret_cast<const float4*>(g)[lane];
        float4 bb = reinterpret_cast<const float4*>(b)[lane];
        v.x = dx*rs*gg.x + bb.x; v.y = dy*rs*gg.y + bb.y;
        v.z = dz*rs*gg.z + bb.z; v.w = dw*rs*gg.w + bb.w;
    }
    float t[4] = {v.x, v.y, v.z, v.w};
    split_store4(oh + row*DIM + lane*4, ol + row*DIM + lane*4, t);
}

// ---------------- zero column sums -------------------------------------------
__global__ void zero_colsum_kernel(){
    g_colsum[blockIdx.x*blockDim.x + threadIdx.x] = 0.f;
}

// ---------------- tiled attention: q staged in smem --------------------------
// block = (batch, 8x8 query tile); smem = 10x10 q-neighborhood (51.2 KB fp32)
#define ATT_SMEM (100*128*4)
__global__ void __launch_bounds__(256) attn_tiled(
    const float* __restrict__ rpb, const float* __restrict__ tau,
    float* __restrict__ attn_out)
{
    extern __shared__ float sq[];
    const int tid = threadIdx.x, warp = tid >> 5, lane = tid & 31;
    const int b    = blockIdx.x >> 6;
    const int tile = blockIdx.x & 63;
    const int th0 = (tile >> 3) << 3, tw0 = (tile & 7) << 3;

    // stage q rows for the clamped neighborhood
    for (int idx = tid; idx < 100*32; idx += 256){
        const int cell = idx >> 5, f4 = idx & 31;
        const int i = cell / 10, j = cell - i*10;
        const int gr = th0 - 1 + i, gc = tw0 - 1 + j;
        if ((unsigned)gr < 64 && (unsigned)gc < 64)
            *reinterpret_cast<float4*>(sq + cell*128 + f4*4) =
                *reinterpret_cast<const float4*>(
                    g_q + ((size_t)b*NPIX_OUT + gr*WO + gc)*DIM + f4*4);
    }
    __syncthreads();

    const float scale = expf(tau[0]);
    for (int tsk = warp; tsk < 256; tsk += 8){
        const int g  = tsk >> 6, lq = tsk & 63;
        const int h = th0 + (lq >> 3), w = tw0 + (lq & 7);
        const int ga = g >> 1, gb = g & 1;
        const int pix = (2*h + ga)*WI + 2*w + gb;
        const float4 kv = reinterpret_cast<const float4*>(
            g_k + ((size_t)b*NPIX_IN + pix)*DIM)[lane];
        const int ch = min(max(h,1), HO-2), cw = min(max(w,1), WO-2);

        float p[9];
        float m = -1e30f;
#pragma unroll
        for (int t = 0; t < 9; t++){
            const int nh = ch + t/3 - 1, nw = cw + t%3 - 1;
            const int cell = (nh - (th0-1))*10 + (nw - (tw0-1));
            const float4 q4 = *reinterpret_cast<const float4*>(sq + cell*128 + lane*4);
            float d = kv.x*q4.x + kv.y*q4.y + kv.z*q4.z + kv.w*q4.w;
            d = wredsum(d);
            const float val = (d + rpb[g*9 + t]) * scale;
            p[t] = val;
            m = fmaxf(m, val);
        }
        float s = 0.f;
#pragma unroll
        for (int t = 0; t < 9; t++){ p[t] = expf(p[t] - m); s += p[t]; }
        const float inv = 1.f/s;
#pragma unroll
        for (int t = 0; t < 9; t++) p[t] = p[t]*inv + 1e-6f;

        if (lane == 0){
            const int id = ((b*4 + g) << 12) + (h << 6) + w;
            float* ao = attn_out + (size_t)id*9;
#pragma unroll
            for (int t = 0; t < 9; t++) ao[t] = p[t];
#pragma unroll
            for (int t = 0; t < 9; t++){
                const int nh = ch + t/3 - 1, nw = cw + t%3 - 1;
                atomicAdd(&g_colsum[b*NPIX_OUT + nh*WO + nw], p[t]);
            }
        }
    }
}

// ---------------- tiled aggregation: v staged in smem ------------------------
// block = (batch, 4x8 query tile); smem = 4 groups x 6x10 v rows (122.9 KB)
#define UPD_SMEM (240*128*4)
__global__ void __launch_bounds__(256) upd_tiled(
    const float* __restrict__ attn_in, float* __restrict__ acol_out)
{
    extern __shared__ float sv[];
    const int tid = threadIdx.x, warp = tid >> 5, lane = tid & 31;
    const int b    = blockIdx.x >> 7;
    const int tile = blockIdx.x & 127;
    const int th0 = (tile >> 3) << 2, tw0 = (tile & 7) << 3;

    // stage v rows for all 4 groups
    for (int idx = tid; idx < 240*32; idx += 256){
        const int cell = idx >> 5, f4 = idx & 31;
        const int g = cell / 60, rc = cell - g*60;
        const int i = rc / 10, j = rc - i*10;
        const int gr = th0 - 1 + i, gc = tw0 - 1 + j;
        if ((unsigned)gr < 64 && (unsigned)gc < 64){
            const int ga = g >> 1, gb = g & 1;
            const int pix = (2*gr + ga)*WI + 2*gc + gb;
            *reinterpret_cast<float4*>(sv + cell*128 + f4*4) =
                *reinterpret_cast<const float4*>(
                    g_v + ((size_t)b*NPIX_IN + pix)*DIM + f4*4);
        }
    }
    __syncthreads();

    for (int tsk = warp; tsk < 32; tsk += 8){
        const int h = th0 + (tsk >> 3), w = tw0 + (tsk & 7);
        const int hw = (h << 6) + w;
        const int ch = min(max(h,1), HO-2), cw = min(max(w,1), WO-2);

        float inv_dn[9];
#pragma unroll
        for (int t = 0; t < 9; t++){
            const int nh = ch + t/3 - 1, nw = cw + t%3 - 1;
            inv_dn[t] = 1.0f / (g_colsum[b*NPIX_OUT + nh*WO + nw] + 1e-8f);
        }
        float4 acc = make_float4(0.f,0.f,0.f,0.f);
#pragma unroll
        for (int g = 0; g < 4; g++){
            const size_t base = ((size_t)((b*4 + g)*NPIX_OUT) + hw)*9;
            const float* ab = attn_in + base;
            float* cb = acol_out + base;
#pragma unroll
            for (int t = 0; t < 9; t++){
                const float coeff = ab[t] * inv_dn[t];
                if (lane == 0) cb[t] = coeff;
                const int nh = ch + t/3 - 1, nw = cw + t%3 - 1;
                const int cell = g*60 + (nh - (th0-1))*10 + (nw - (tw0-1));
                const float4 vv = *reinterpret_cast<const float4*>(sv + cell*128 + lane*4);
                acc.x += coeff*vv.x; acc.y += coeff*vv.y;
                acc.z += coeff*vv.z; acc.w += coeff*vv.w;
            }
        }
        const int id = (b << 12) + hw;
        float4* xo = reinterpret_cast<float4*>(g_xout + (size_t)id*DIM);
        float4 v = xo[lane];
        v.x += acc.x; v.y += acc.y; v.z += acc.z; v.w += acc.w;
        xo[lane] = v;
        float t4[4] = {v.x, v.y, v.z, v.w};
        split_store4(g_xo_h + (size_t)id*DIM + lane*4,
                     g_xo_l + (size_t)id*DIM + lane*4, t4);
    }
}

// ---------------- launch ------------------------------------------------------
extern "C" void kernel_launch(void* const* d_in, const int* in_sizes, int n_in,
                              void* d_out, int out_size)
{
    const float* x      = (const float*)d_in[0];
    const float* convw  = (const float*)d_in[1];
    const float* q_w    = (const float*)d_in[2];
    const float* k_w    = (const float*)d_in[3];
    const float* v_w    = (const float*)d_in[4];
    const float* w1     = (const float*)d_in[5];
    const float* b1     = (const float*)d_in[6];
    const float* w2     = (const float*)d_in[7];
    const float* b2     = (const float*)d_in[8];
    const float* lin_g  = (const float*)d_in[9];
    const float* lin_b  = (const float*)d_in[10];
    const float* lout_g = (const float*)d_in[11];
    const float* lout_b = (const float*)d_in[12];
    const float* tau    = (const float*)d_in[13];
    const float* rpb    = (const float*)d_in[14];

    float* out      = (float*)d_out;
    float* out_x    = out;
    float* out_attn = out + (size_t)NROWS_OUT*DIM;
    float* out_acol = out_attn + (size_t)BATCH*4*NPIX_OUT*9;

    float *pk, *pv, *pq, *pxout;
    cudaGetSymbolAddress((void**)&pk,    g_k);
    cudaGetSymbolAddress((void**)&pv,    g_v);
    cudaGetSymbolAddress((void**)&pq,    g_q);
    cudaGetSymbolAddress((void**)&pxout, g_xout);
    __nv_bfloat16 *pxh,*pxl,*plih,*plil,*poh,*pol,*pqh,*pql,*phh,*phl;
    __nv_bfloat16 *wqh,*wql,*wkh,*wkl,*wvh,*wvl,*w1h,*w1l,*w2h,*w2l;
    cudaGetSymbolAddress((void**)&pxh,  g_x_h);   cudaGetSymbolAddress((void**)&pxl,  g_x_l);
    cudaGetSymbolAddress((void**)&plih, g_xli_h); cudaGetSymbolAddress((void**)&plil, g_xli_l);
    cudaGetSymbolAddress((void**)&poh,  g_xo_h);  cudaGetSymbolAddress((void**)&pol,  g_xo_l);
    cudaGetSymbolAddress((void**)&pqh,  g_xq_h);  cudaGetSymbolAddress((void**)&pql,  g_xq_l);
    cudaGetSymbolAddress((void**)&phh,  g_hh_h);  cudaGetSymbolAddress((void**)&phl,  g_hh_l);
    cudaGetSymbolAddress((void**)&wqh,  g_wq_h);  cudaGetSymbolAddress((void**)&wql,  g_wq_l);
    cudaGetSymbolAddress((void**)&wkh,  g_wk_h);  cudaGetSymbolAddress((void**)&wkl,  g_wk_l);
    cudaGetSymbolAddress((void**)&wvh,  g_wv_h);  cudaGetSymbolAddress((void**)&wvl,  g_wv_l);
    cudaGetSymbolAddress((void**)&w1h,  g_w1_h);  cudaGetSymbolAddress((void**)&w1l,  g_w1_l);
    cudaGetSymbolAddress((void**)&w2h,  g_w2_h);  cudaGetSymbolAddress((void**)&w2l,  g_w2_l);

    cudaFuncSetAttribute(gemm_mma, cudaFuncAttributeMaxDynamicSharedMemorySize, SMEM_MMA);
    cudaFuncSetAttribute(conv_mma, cudaFuncAttributeMaxDynamicSharedMemorySize, SMEM_MMA);
    cudaFuncSetAttribute(attn_tiled, cudaFuncAttributeMaxDynamicSharedMemorySize, ATT_SMEM);
    cudaFuncSetAttribute(upd_tiled, cudaFuncAttributeMaxDynamicSharedMemorySize, UPD_SMEM);

    // ---- preprocessing ----
    conv_split_kernel<<<(9*DIM*DIM + 255)/256, 256>>>(convw);
    tsplit_kernel<<<(DIM*DIM)/256, 256>>>(q_w, wqh, wql, DIM, DIM);
    tsplit_kernel<<<(DIM*DIM)/256, 256>>>(k_w, wkh, wkl, DIM, DIM);
    tsplit_kernel<<<(DIM*DIM)/256, 256>>>(v_w, wvh, wvl, DIM, DIM);
    tsplit_kernel<<<(2*DIM*DIM)/256, 256>>>(w1, w1h, w1l, DIM, 2*DIM);   // -> [256,128]
    tsplit_kernel<<<(2*DIM*DIM)/256, 256>>>(w2, w2h, w2l, 2*DIM, DIM);   // -> [128,256]
    split_kernel<false><<<NROWS_IN/8, 256>>>(x, pxh, pxl, nullptr, nullptr);
    split_kernel<true ><<<NROWS_IN/8, 256>>>(x, plih, plil, lin_g, lin_b);

    // k = LN_in(x) @ k_w ; v = x @ v_w
    gemm_mma<<<NROWS_IN/128, 256, SMEM_MMA>>>(plih, plil, 128, wkh, wkl,
        nullptr, nullptr, nullptr, pk, 128, nullptr, nullptr, nullptr, nullptr, 0,
        EPI_STORE, 0);
    gemm_mma<<<NROWS_IN/128, 256, SMEM_MMA>>>(pxh, pxl, 128, wvh, wvl,
        nullptr, nullptr, nullptr, pv, 128, nullptr, nullptr, nullptr, nullptr, 0,
        EPI_STORE, 0);
    conv_mma<<<NROWS_OUT/128, 256, SMEM_MMA>>>(lout_g, lout_b);

    for (int it = 0; it < 3; it++){
        zero_colsum_kernel<<<(BATCH*NPIX_OUT)/256, 256>>>();
        // q = LN(x_out) @ q_w
        gemm_mma<<<NROWS_OUT/128, 256, SMEM_MMA>>>(pqh, pql, 128, wqh, wql,
            nullptr, nullptr, nullptr, pq, 128, nullptr, nullptr, nullptr, nullptr, 0,
            EPI_STORE, 0);
        attn_tiled<<<BATCH*64, 256, ATT_SMEM>>>(rpb, tau, out_attn);
        upd_tiled<<<BATCH*128, 256, UPD_SMEM>>>(out_attn, out_acol);
        // h = gelu(x_out @ w1 + b1) -> bf16 split
        gemm_mma<<<dim3(NROWS_OUT/128, 2), 256, SMEM_MMA>>>(poh, pol, 128, w1h, w1l,
            b1, nullptr, nullptr, nullptr, 0, nullptr, nullptr, phh, phl, 256,
            EPI_GELU, 0);
        // x_out += LN(h @ w2 + b2); xq = LN(x_out) split
        gemm_mma<<<NROWS_OUT/128, 256, SMEM_MMA>>>(phh, phl, 256, w2h, w2l,
            b2, lout_g, lout_b, nullptr, 0, pxout, out_x, pqh, pql, 128,
            EPI_LNRES, it == 2 ? 1 : 0);
    }
    (void)in_sizes; (void)n_in; (void)out_size;
}

// round 13
// speedup vs baseline: 1.4383x; 1.4383x over previous
#include <cuda_runtime.h>
#include <cuda_bf16.h>
#include <math.h>
#include <stdint.h>

#define BATCH 4
#define HI 128
#define WI 128
#define HO 64
#define WO 64
#define DIM 128
#define NPIX_IN  (HI*WI)
#define NPIX_OUT (HO*WO)
#define NROWS_IN  (BATCH*NPIX_IN)   // 65536
#define NROWS_OUT (BATCH*NPIX_OUT)  // 16384

// ---------------- scratch (device globals) ----------------------------------
__device__ float g_k   [(size_t)NROWS_IN*DIM];
__device__ float g_v   [(size_t)NROWS_IN*DIM];
__device__ float g_q   [(size_t)NROWS_OUT*DIM];
__device__ float g_xout[(size_t)NROWS_OUT*DIM];
__device__ float g_colsum[BATCH*NPIX_OUT];

// bf16 split buffers (hi/lo)
__device__ __align__(16) __nv_bfloat16 g_x_h  [(size_t)NROWS_IN*DIM];
__device__ __align__(16) __nv_bfloat16 g_x_l  [(size_t)NROWS_IN*DIM];
__device__ __align__(16) __nv_bfloat16 g_xli_h[(size_t)NROWS_IN*DIM];   // LN_in(x)
__device__ __align__(16) __nv_bfloat16 g_xli_l[(size_t)NROWS_IN*DIM];
__device__ __align__(16) __nv_bfloat16 g_xo_h [(size_t)NROWS_OUT*DIM];  // xout (post-upd)
__device__ __align__(16) __nv_bfloat16 g_xo_l [(size_t)NROWS_OUT*DIM];
__device__ __align__(16) __nv_bfloat16 g_xq_h [(size_t)NROWS_OUT*DIM];  // LN(xout)
__device__ __align__(16) __nv_bfloat16 g_xq_l [(size_t)NROWS_OUT*DIM];
__device__ __align__(16) __nv_bfloat16 g_hh_h [(size_t)NROWS_OUT*2*DIM];
__device__ __align__(16) __nv_bfloat16 g_hh_l [(size_t)NROWS_OUT*2*DIM];
// transposed-split weights [N,K]
__device__ __align__(16) __nv_bfloat16 g_wq_h[DIM*DIM], g_wq_l[DIM*DIM];
__device__ __align__(16) __nv_bfloat16 g_wk_h[DIM*DIM], g_wk_l[DIM*DIM];
__device__ __align__(16) __nv_bfloat16 g_wv_h[DIM*DIM], g_wv_l[DIM*DIM];
__device__ __align__(16) __nv_bfloat16 g_w1_h[2*DIM*DIM], g_w1_l[2*DIM*DIM]; // [256,128]
__device__ __align__(16) __nv_bfloat16 g_w2_h[2*DIM*DIM], g_w2_l[2*DIM*DIM]; // [128,256]
// conv weights per tap: [tap][o][i] bf16 split
__device__ __align__(16) __nv_bfloat16 g_cw_h[9*DIM*DIM], g_cw_l[9*DIM*DIM];

// ---------------- helpers ----------------------------------------------------
static __device__ __forceinline__ float wredsum(float v){
#pragma unroll
    for (int o = 16; o > 0; o >>= 1) v += __shfl_xor_sync(0xffffffffu, v, o);
    return v;
}
static __device__ __forceinline__ float geluf(float x){
    return 0.5f * x * (1.0f + erff(x * 0.70710678118654752440f));
}
static __device__ __forceinline__ uint32_t smem_u32(const void* p){
    uint32_t a;
    asm("{ .reg .u64 t; cvta.to.shared.u64 t, %1; cvt.u32.u64 %0, t; }" : "=r"(a) : "l"(p));
    return a;
}
static __device__ __forceinline__ void split2(float v, __nv_bfloat16& h, __nv_bfloat16& l){
    h = __float2bfloat16(v);
    l = __float2bfloat16(v - __bfloat162float(h));
}
static __device__ __forceinline__ void split_store4(
    __nv_bfloat16* ph, __nv_bfloat16* pl, const float* v)
{
    __nv_bfloat16 h[4], l[4];
#pragma unroll
    for (int i = 0; i < 4; i++) split2(v[i], h[i], l[i]);
    *reinterpret_cast<uint2*>(ph) = *reinterpret_cast<const uint2*>(h);
    *reinterpret_cast<uint2*>(pl) = *reinterpret_cast<const uint2*>(l);
}

// ---------------- mma primitives (baseline PTX: sm_80-compatible) -----------
static __device__ __forceinline__ void ldsm_x4(uint32_t* r, uint32_t addr){
    asm volatile("ldmatrix.sync.aligned.m8n8.x4.shared.b16 {%0,%1,%2,%3}, [%4];"
        : "=r"(r[0]), "=r"(r[1]), "=r"(r[2]), "=r"(r[3]) : "r"(addr));
}
static __device__ __forceinline__ void mma16816(
    float* c, const uint32_t* a, uint32_t b0, uint32_t b1)
{
    asm volatile(
        "mma.sync.aligned.m16n8k16.row.col.f32.bf16.bf16.f32 "
        "{%0,%1,%2,%3}, {%4,%5,%6,%7}, {%8,%9}, {%0,%1,%2,%3};"
        : "+f"(c[0]), "+f"(c[1]), "+f"(c[2]), "+f"(c[3])
        : "r"(a[0]), "r"(a[1]), "r"(a[2]), "r"(a[3]), "r"(b0), "r"(b1));
}

#define EPI_STORE 0
#define EPI_GELU  1
#define EPI_LNRES 2

#define TSTRIDE 72                      // bf16 elements per smem row (pad 64->72)
#define TBYTES  (128*TSTRIDE*2)         // 18432 bytes per tile
#define OFF_AH  0
#define OFF_AL  (TBYTES)
#define OFF_BH  (2*TBYTES)
#define OFF_BL  (3*TBYTES)
#define SMEM_MMA (4*TBYTES)             // 73728

// ---------------- bf16-3x tensor-core GEMM -----------------------------------
// D[128 tile, 128 tile] = A @ B^T; A[M,Ktot] hi/lo, B[N,Ktot] hi/lo (row-major).
// zbuf: optional 16384-float buffer zeroed at kernel start (colsum fold).
__global__ void __launch_bounds__(256,2) gemm_mma(
    const __nv_bfloat16* __restrict__ Ah, const __nv_bfloat16* __restrict__ Al, int Ktot,
    const __nv_bfloat16* __restrict__ Bh, const __nv_bfloat16* __restrict__ Bl,
    const float* __restrict__ bias,
    const float* __restrict__ lng, const float* __restrict__ lnb,
    float* __restrict__ C, int ldc,
    float* __restrict__ res, float* __restrict__ fin,
    __nv_bfloat16* __restrict__ ohi, __nv_bfloat16* __restrict__ olo, int ldo,
    float* __restrict__ zbuf,
    int epi, int writeFinal)
{
    extern __shared__ char sm[];
    const uint32_t smb = smem_u32(sm);
    const int tid = threadIdx.x, wid = tid >> 5, lane = tid & 31;
    const int wm = wid & 3, wn = wid >> 2;
    const int mBase = blockIdx.x * 128;
    const int col0  = blockIdx.y * 128;

    if (zbuf != nullptr && blockIdx.y == 0 && tid < 128)
        zbuf[(size_t)blockIdx.x*128 + tid] = 0.f;

    float acc[2][8][4];
#pragma unroll
    for (int mt = 0; mt < 2; mt++)
#pragma unroll
        for (int nt = 0; nt < 8; nt++)
#pragma unroll
            for (int i = 0; i < 4; i++) acc[mt][nt][i] = 0.f;

    const __nv_bfloat16* Ah0 = Ah + (size_t)mBase*Ktot;
    const __nv_bfloat16* Al0 = Al + (size_t)mBase*Ktot;
    const __nv_bfloat16* Bh0 = Bh + (size_t)col0*Ktot;
    const __nv_bfloat16* Bl0 = Bl + (size_t)col0*Ktot;

    const int aRow = lane & 15, aKh = (lane >> 4) << 3;
    const int bRow = (lane & 7) + ((lane >> 4) << 3);
    const int bKh  = ((lane >> 3) & 1) << 3;

    for (int kc = 0; kc < Ktot; kc += 64){
        __syncthreads();
#pragma unroll
        for (int i = 0; i < 4; i++){
            int u = tid + i*256;
            int m = u >> 3, c8 = (u & 7) << 3;
            size_t go = (size_t)m*Ktot + kc + c8;
            int so = (m*TSTRIDE + c8) << 1;
            *reinterpret_cast<uint4*>(sm + OFF_AH + so) = *reinterpret_cast<const uint4*>(Ah0 + go);
            *reinterpret_cast<uint4*>(sm + OFF_AL + so) = *reinterpret_cast<const uint4*>(Al0 + go);
            *reinterpret_cast<uint4*>(sm + OFF_BH + so) = *reinterpret_cast<const uint4*>(Bh0 + go);
            *reinterpret_cast<uint4*>(sm + OFF_BL + so) = *reinterpret_cast<const uint4*>(Bl0 + go);
        }
        __syncthreads();

#pragma unroll
        for (int ks = 0; ks < 4; ks++){
            uint32_t ah[2][4], al[2][4];
#pragma unroll
            for (int mt = 0; mt < 2; mt++){
                const int eoff = ((wm*32 + mt*16 + aRow)*TSTRIDE + ks*16 + aKh) << 1;
                ldsm_x4(ah[mt], smb + OFF_AH + eoff);
                ldsm_x4(al[mt], smb + OFF_AL + eoff);
            }
#pragma unroll
            for (int np = 0; np < 4; np++){
                const int eoff = ((wn*64 + np*16 + bRow)*TSTRIDE + ks*16 + bKh) << 1;
                uint32_t bh4[4], bl4[4];
                ldsm_x4(bh4, smb + OFF_BH + eoff);
                ldsm_x4(bl4, smb + OFF_BL + eoff);
#pragma unroll
                for (int mt = 0; mt < 2; mt++){
#pragma unroll
                    for (int hf = 0; hf < 2; hf++){
                        float* c = acc[mt][np*2 + hf];
                        mma16816(c, ah[mt], bh4[hf*2], bh4[hf*2+1]);
                        mma16816(c, al[mt], bh4[hf*2], bh4[hf*2+1]);
                        mma16816(c, ah[mt], bl4[hf*2], bl4[hf*2+1]);
                    }
                }
            }
        }
    }

    // ---------------- epilogues ----------------
    if (epi == EPI_STORE){
#pragma unroll
        for (int mt = 0; mt < 2; mt++){
            const int row = mBase + wm*32 + mt*16 + (lane >> 2);
#pragma unroll
            for (int nt = 0; nt < 8; nt++){
                const int colg = col0 + wn*64 + nt*8 + ((lane & 3) << 1);
                *reinterpret_cast<float2*>(C + (size_t)row*ldc + colg) =
                    make_float2(acc[mt][nt][0], acc[mt][nt][1]);
                *reinterpret_cast<float2*>(C + (size_t)(row+8)*ldc + colg) =
                    make_float2(acc[mt][nt][2], acc[mt][nt][3]);
            }
        }
    } else if (epi == EPI_GELU){
#pragma unroll
        for (int mt = 0; mt < 2; mt++){
            const int row = mBase + wm*32 + mt*16 + (lane >> 2);
#pragma unroll
            for (int nt = 0; nt < 8; nt++){
                const int colg = col0 + wn*64 + nt*8 + ((lane & 3) << 1);
                const float b0 = bias[colg], b1 = bias[colg+1];
                float v0 = geluf(acc[mt][nt][0] + b0);
                float v1 = geluf(acc[mt][nt][1] + b1);
                float v2 = geluf(acc[mt][nt][2] + b0);
                float v3 = geluf(acc[mt][nt][3] + b1);
                __nv_bfloat16 h0,l0,h1,l1;
                split2(v0,h0,l0); split2(v1,h1,l1);
                *reinterpret_cast<__nv_bfloat162*>(ohi + (size_t)row*ldo + colg) = {h0,h1};
                *reinterpret_cast<__nv_bfloat162*>(olo + (size_t)row*ldo + colg) = {l0,l1};
                split2(v2,h0,l0); split2(v3,h1,l1);
                *reinterpret_cast<__nv_bfloat162*>(ohi + (size_t)(row+8)*ldo + colg) = {h0,h1};
                *reinterpret_cast<__nv_bfloat162*>(olo + (size_t)(row+8)*ldo + colg) = {l0,l1};
            }
        }
    } else { // EPI_LNRES
        __syncthreads();
        float* sf = reinterpret_cast<float*>(sm);
#pragma unroll
        for (int mt = 0; mt < 2; mt++){
            const int lr = wm*32 + mt*16 + (lane >> 2);
#pragma unroll
            for (int nt = 0; nt < 8; nt++){
                const int lc = wn*64 + nt*8 + ((lane & 3) << 1);
                const float b0 = bias[lc], b1 = bias[lc+1];
                sf[lr*132 + lc]       = acc[mt][nt][0] + b0;
                sf[lr*132 + lc + 1]   = acc[mt][nt][1] + b1;
                sf[(lr+8)*132 + lc]   = acc[mt][nt][2] + b0;
                sf[(lr+8)*132 + lc+1] = acc[mt][nt][3] + b1;
            }
        }
        __syncthreads();
        const float4 gg = reinterpret_cast<const float4*>(lng)[lane];
        const float4 lb = reinterpret_cast<const float4*>(lnb)[lane];
        for (int r = wid*16; r < wid*16 + 16; r++){
            float4 v = *reinterpret_cast<float4*>(sf + r*132 + lane*4);
            float mu = wredsum(v.x+v.y+v.z+v.w) * (1.0f/128.0f);
            float dx=v.x-mu, dy=v.y-mu, dz=v.z-mu, dw=v.w-mu;
            float var = wredsum(dx*dx+dy*dy+dz*dz+dw*dw) * (1.0f/128.0f);
            float rs = rsqrtf(var + 1e-5f);
            const int row = mBase + r;
            float* rp = res + (size_t)row*DIM;
            float4 r4 = reinterpret_cast<float4*>(rp)[lane];
            float o[4];
            o[0] = r4.x + dx*rs*gg.x + lb.x;
            o[1] = r4.y + dy*rs*gg.y + lb.y;
            o[2] = r4.z + dz*rs*gg.z + lb.z;
            o[3] = r4.w + dw*rs*gg.w + lb.w;
            float4 o4 = make_float4(o[0],o[1],o[2],o[3]);
            reinterpret_cast<float4*>(rp)[lane] = o4;
            if (writeFinal)
                reinterpret_cast<float4*>(fin + (size_t)row*DIM)[lane] = o4;
            float mu2 = wredsum(o[0]+o[1]+o[2]+o[3]) * (1.0f/128.0f);
            float e0=o[0]-mu2, e1=o[1]-mu2, e2=o[2]-mu2, e3=o[3]-mu2;
            float var2 = wredsum(e0*e0+e1*e1+e2*e2+e3*e3) * (1.0f/128.0f);
            float rs2 = rsqrtf(var2 + 1e-5f);
            float x2[4];
            x2[0] = e0*rs2*gg.x + lb.x; x2[1] = e1*rs2*gg.y + lb.y;
            x2[2] = e2*rs2*gg.z + lb.z; x2[3] = e3*rs2*gg.w + lb.w;
            split_store4(ohi + (size_t)row*DIM + lane*4,
                         olo + (size_t)row*DIM + lane*4, x2);
        }
    }
}

// ---------------- conv as implicit tensor-core GEMM --------------------------
__global__ void __launch_bounds__(256) conv_mma(
    const float* __restrict__ lng, const float* __restrict__ lnb)
{
    extern __shared__ char sm[];
    const uint32_t smb = smem_u32(sm);
    const int tid = threadIdx.x, wid = tid >> 5, lane = tid & 31;
    const int wm = wid & 3, wn = wid >> 2;
    const int mBase = blockIdx.x * 128;

    float acc[2][8][4];
#pragma unroll
    for (int mt = 0; mt < 2; mt++)
#pragma unroll
        for (int nt = 0; nt < 8; nt++)
#pragma unroll
            for (int i = 0; i < 4; i++) acc[mt][nt][i] = 0.f;

    const int aRow = lane & 15, aKh = (lane >> 4) << 3;
    const int bRow = (lane & 7) + ((lane >> 4) << 3);
    const int bKh  = ((lane >> 3) & 1) << 3;

    for (int tap = 0; tap < 9; tap++){
        const int kh = tap/3 - 1, kw = tap%3 - 1;
        for (int kc = 0; kc < 2; kc++){
            __syncthreads();
#pragma unroll
            for (int i = 0; i < 4; i++){
                int u = tid + i*256;
                int m = u >> 3, c8 = (u & 7) << 3;
                const int p = mBase + m;
                const int b = p >> 12, hw = p & 4095;
                const int h = hw >> 6, w = hw & 63;
                const int hi = 2*h + kh, wi = 2*w + kw;
                uint4 vh = make_uint4(0,0,0,0), vl = make_uint4(0,0,0,0);
                if ((unsigned)hi < HI && (unsigned)wi < WI){
                    size_t go = ((size_t)b*NPIX_IN + hi*WI + wi)*DIM + kc*64 + c8;
                    vh = *reinterpret_cast<const uint4*>(g_x_h + go);
                    vl = *reinterpret_cast<const uint4*>(g_x_l + go);
                }
                int so = (m*TSTRIDE + c8) << 1;
                *reinterpret_cast<uint4*>(sm + OFF_AH + so) = vh;
                *reinterpret_cast<uint4*>(sm + OFF_AL + so) = vl;
                size_t gb = (size_t)tap*DIM*DIM + (size_t)m*DIM + kc*64 + c8;
                *reinterpret_cast<uint4*>(sm + OFF_BH + so) =
                    *reinterpret_cast<const uint4*>(g_cw_h + gb);
                *reinterpret_cast<uint4*>(sm + OFF_BL + so) =
                    *reinterpret_cast<const uint4*>(g_cw_l + gb);
            }
            __syncthreads();
#pragma unroll
            for (int ks = 0; ks < 4; ks++){
                uint32_t ah[2][4], al[2][4];
#pragma unroll
                for (int mt = 0; mt < 2; mt++){
                    const int eoff = ((wm*32 + mt*16 + aRow)*TSTRIDE + ks*16 + aKh) << 1;
                    ldsm_x4(ah[mt], smb + OFF_AH + eoff);
                    ldsm_x4(al[mt], smb + OFF_AL + eoff);
                }
#pragma unroll
                for (int np = 0; np < 4; np++){
                    const int eoff = ((wn*64 + np*16 + bRow)*TSTRIDE + ks*16 + bKh) << 1;
                    uint32_t bh4[4], bl4[4];
                    ldsm_x4(bh4, smb + OFF_BH + eoff);
                    ldsm_x4(bl4, smb + OFF_BL + eoff);
#pragma unroll
                    for (int mt = 0; mt < 2; mt++){
#pragma unroll
                        for (int hf = 0; hf < 2; hf++){
                            float* c = acc[mt][np*2 + hf];
                            mma16816(c, ah[mt], bh4[hf*2], bh4[hf*2+1]);
                            mma16816(c, al[mt], bh4[hf*2], bh4[hf*2+1]);
                            mma16816(c, ah[mt], bl4[hf*2], bl4[hf*2+1]);
                        }
                    }
                }
            }
        }
    }

    __syncthreads();
    float* sf = reinterpret_cast<float*>(sm);
#pragma unroll
    for (int mt = 0; mt < 2; mt++){
        const int lr = wm*32 + mt*16 + (lane >> 2);
#pragma unroll
        for (int nt = 0; nt < 8; nt++){
            const int lc = wn*64 + nt*8 + ((lane & 3) << 1);
            sf[lr*132 + lc]       = acc[mt][nt][0];
            sf[lr*132 + lc + 1]   = acc[mt][nt][1];
            sf[(lr+8)*132 + lc]   = acc[mt][nt][2];
            sf[(lr+8)*132 + lc+1] = acc[mt][nt][3];
        }
    }
    __syncthreads();
    const float4 gg = reinterpret_cast<const float4*>(lng)[lane];
    const float4 lb = reinterpret_cast<const float4*>(lnb)[lane];
    for (int r = wid*16; r < wid*16 + 16; r++){
        float4 v = *reinterpret_cast<float4*>(sf + r*132 + lane*4);
        float mu = wredsum(v.x+v.y+v.z+v.w) * (1.0f/128.0f);
        float dx=v.x-mu, dy=v.y-mu, dz=v.z-mu, dw=v.w-mu;
        float var = wredsum(dx*dx+dy*dy+dz*dz+dw*dw) * (1.0f/128.0f);
        float rs = rsqrtf(var + 1e-5f);
        const int row = mBase + r;
        float o[4];
        o[0] = dx*rs*gg.x + lb.x; o[1] = dy*rs*gg.y + lb.y;
        o[2] = dz*rs*gg.z + lb.z; o[3] = dw*rs*gg.w + lb.w;
        reinterpret_cast<float4*>(g_xout + (size_t)row*DIM)[lane] =
            make_float4(o[0],o[1],o[2],o[3]);
        float mu2 = wredsum(o[0]+o[1]+o[2]+o[3]) * (1.0f/128.0f);
        float e0=o[0]-mu2, e1=o[1]-mu2, e2=o[2]-mu2, e3=o[3]-mu2;
        float var2 = wredsum(e0*e0+e1*e1+e2*e2+e3*e3) * (1.0f/128.0f);
        float rs2 = rsqrtf(var2 + 1e-5f);
        float x2[4];
        x2[0] = e0*rs2*gg.x + lb.x; x2[1] = e1*rs2*gg.y + lb.y;
        x2[2] = e2*rs2*gg.z + lb.z; x2[3] = e3*rs2*gg.w + lb.w;
        split_store4(g_xq_h + (size_t)row*DIM + lane*4,
                     g_xq_l + (size_t)row*DIM + lane*4, x2);
    }
}

// ---------------- conv weight split: [o][i][tap] -> [tap][o][i] hi/lo --------
__global__ void conv_split_kernel(const float* __restrict__ cw){
    int idx = blockIdx.x*256 + threadIdx.x;
    if (idx >= 9*DIM*DIM) return;
    int o   = idx / (DIM*9);
    int rem = idx - o*(DIM*9);
    int i   = rem / 9;
    int tap = rem - i*9;
    __nv_bfloat16 h, l;
    split2(cw[idx], h, l);
    g_cw_h[(size_t)tap*DIM*DIM + o*DIM + i] = h;
    g_cw_l[(size_t)tap*DIM*DIM + o*DIM + i] = l;
}

// ---------------- weight transpose + split: in[K,N] -> out[N,K] hi/lo --------
__global__ void tsplit_kernel(const float* __restrict__ in,
                              __nv_bfloat16* __restrict__ oh,
                              __nv_bfloat16* __restrict__ ol,
                              int K, int N)
{
    int idx = blockIdx.x*256 + threadIdx.x;
    if (idx >= K*N) return;
    int k = idx / N, n = idx - k*N;
    __nv_bfloat16 h, l;
    split2(in[idx], h, l);
    oh[(size_t)n*K + k] = h;
    ol[(size_t)n*K + k] = l;
}

// ---------------- combined split: x -> (x_h,x_l) and LN_in(x) -> (li_h,li_l) -
__global__ void __launch_bounds__(256) split_both_kernel(
    const float* __restrict__ in,
    __nv_bfloat16* __restrict__ xh, __nv_bfloat16* __restrict__ xl,
    __nv_bfloat16* __restrict__ lih, __nv_bfloat16* __restrict__ lil,
    const float* __restrict__ g, const float* __restrict__ b)
{
    const int lane = threadIdx.x & 31, warp = threadIdx.x >> 5;
    const size_t row = (size_t)blockIdx.x*8 + warp;
    float4 v = reinterpret_cast<const float4*>(in + row*DIM)[lane];
    float t[4] = {v.x, v.y, v.z, v.w};
    split_store4(xh + row*DIM + lane*4, xl + row*DIM + lane*4, t);
    float mu = wredsum(v.x+v.y+v.z+v.w) * (1.0f/DIM);
    float dx=v.x-mu, dy=v.y-mu, dz=v.z-mu, dw=v.w-mu;
    float var = wredsum(dx*dx+dy*dy+dz*dz+dw*dw) * (1.0f/DIM);
    float rs = rsqrtf(var + 1e-5f);
    float4 gg = reinterpret_cast<const float4*>(g)[lane];
    float4 bb = reinterpret_cast<const float4*>(b)[lane];
    float u[4];
    u[0] = dx*rs*gg.x + bb.x; u[1] = dy*rs*gg.y + bb.y;
    u[2] = dz*rs*gg.z + bb.z; u[3] = dw*rs*gg.w + bb.w;
    split_store4(lih + row*DIM + lane*4, lil + row*DIM + lane*4, u);
}

// ---------------- attention: scores + softmax + eps + colsum atomics ---------
__global__ void attn_kernel(const float* __restrict__ rpb,
                            const float* __restrict__ tau,
                            float* __restrict__ attn_out)
{
    const int tid = threadIdx.x, warp = tid >> 5, lane = tid & 31;
    const int id  = blockIdx.x*4 + warp;
    const int b   = id >> 14;
    const int rem = id & 16383;
    const int g   = rem >> 12;
    const int hw  = rem & 4095;
    const int h = hw >> 6, w = hw & 63;
    const int ga = g >> 1, gb = g & 1;
    const int pix = (2*h + ga)*WI + 2*w + gb;
    const float4 kv = reinterpret_cast<const float4*>(g_k + ((size_t)b*NPIX_IN + pix)*DIM)[lane];
    const float scale = expf(tau[0]);
    const int ch = min(max(h,1), HO-2), cw = min(max(w,1), WO-2);

    float p[9];
    float m = -1e30f;
#pragma unroll
    for (int t = 0; t < 9; t++){
        const int nh = ch + t/3 - 1, nw = cw + t%3 - 1;
        const float4 q4 = reinterpret_cast<const float4*>(g_q + ((size_t)b*NPIX_OUT + nh*WO + nw)*DIM)[lane];
        float d = kv.x*q4.x + kv.y*q4.y + kv.z*q4.z + kv.w*q4.w;
        d = wredsum(d);
        const float val = (d + rpb[g*9 + t]) * scale;
        p[t] = val;
        m = fmaxf(m, val);
    }
    float s = 0.f;
#pragma unroll
    for (int t = 0; t < 9; t++){ p[t] = expf(p[t] - m); s += p[t]; }
    const float inv = 1.f/s;
#pragma unroll
    for (int t = 0; t < 9; t++) p[t] = p[t]*inv + 1e-6f;

    if (lane == 0){
        float* ao = attn_out + (size_t)id*9;
#pragma unroll
        for (int t = 0; t < 9; t++) ao[t] = p[t];
#pragma unroll
        for (int t = 0; t < 9; t++){
            const int nh = ch + t/3 - 1, nw = cw + t%3 - 1;
            atomicAdd(&g_colsum[b*NPIX_OUT + nh*WO + nw], p[t]);
        }
    }
}

// ---------------- aggregation: A_col + upd + residual + xout split -----------
__global__ void upd_kernel(const float* __restrict__ attn_in,
                           float* __restrict__ acol_out)
{
    const int tid = threadIdx.x, warp = tid >> 5, lane = tid & 31;
    const int id = blockIdx.x*4 + warp;
    const int b  = id >> 12;
    const int hw = id & 4095;
    const int h = hw >> 6, w = hw & 63;
    const int ch = min(max(h,1), HO-2), cw = min(max(w,1), WO-2);

    float inv_dn[9];
#pragma unroll
    for (int t = 0; t < 9; t++){
        const int nh = ch + t/3 - 1, nw = cw + t%3 - 1;
        inv_dn[t] = 1.0f / (g_colsum[b*NPIX_OUT + nh*WO + nw] + 1e-8f);
    }
    float4 acc = make_float4(0.f,0.f,0.f,0.f);
#pragma unroll
    for (int g = 0; g < 4; g++){
        const int ga = g >> 1, gb = g & 1;
        const size_t base = ((size_t)((b*4 + g)*NPIX_OUT) + hw)*9;
        const float* ab = attn_in + base;
        float* cb = acol_out + base;
#pragma unroll
        for (int t = 0; t < 9; t++){
            const float coeff = ab[t] * inv_dn[t];
            if (lane == 0) cb[t] = coeff;
            const int nh = ch + t/3 - 1, nw = cw + t%3 - 1;
            const int pix = (2*nh + ga)*WI + 2*nw + gb;
            const float4 vv = reinterpret_cast<const float4*>(g_v + ((size_t)b*NPIX_IN + pix)*DIM)[lane];
            acc.x += coeff*vv.x; acc.y += coeff*vv.y; acc.z += coeff*vv.z; acc.w += coeff*vv.w;
        }
    }
    float4* xo = reinterpret_cast<float4*>(g_xout + (size_t)id*DIM);
    float4 v = xo[lane];
    v.x += acc.x; v.y += acc.y; v.z += acc.z; v.w += acc.w;
    xo[lane] = v;
    float t4[4] = {v.x, v.y, v.z, v.w};
    split_store4(g_xo_h + (size_t)id*DIM + lane*4,
                 g_xo_l + (size_t)id*DIM + lane*4, t4);
}

// ---------------- launch ------------------------------------------------------
extern "C" void kernel_launch(void* const* d_in, const int* in_sizes, int n_in,
                              void* d_out, int out_size)
{
    const float* x      = (const float*)d_in[0];
    const float* convw  = (const float*)d_in[1];
    const float* q_w    = (const float*)d_in[2];
    const float* k_w    = (const float*)d_in[3];
    const float* v_w    = (const float*)d_in[4];
    const float* w1     = (const float*)d_in[5];
    const float* b1     = (const float*)d_in[6];
    const float* w2     = (const float*)d_in[7];
    const float* b2     = (const float*)d_in[8];
    const float* lin_g  = (const float*)d_in[9];
    const float* lin_b  = (const float*)d_in[10];
    const float* lout_g = (const float*)d_in[11];
    const float* lout_b = (const float*)d_in[12];
    const float* tau    = (const float*)d_in[13];
    const float* rpb    = (const float*)d_in[14];

    float* out      = (float*)d_out;
    float* out_x    = out;
    float* out_attn = out + (size_t)NROWS_OUT*DIM;
    float* out_acol = out_attn + (size_t)BATCH*4*NPIX_OUT*9;

    float *pk, *pv, *pq, *pxout, *pcs;
    cudaGetSymbolAddress((void**)&pk,    g_k);
    cudaGetSymbolAddress((void**)&pv,    g_v);
    cudaGetSymbolAddress((void**)&pq,    g_q);
    cudaGetSymbolAddress((void**)&pxout, g_xout);
    cudaGetSymbolAddress((void**)&pcs,   g_colsum);
    __nv_bfloat16 *pxh,*pxl,*plih,*plil,*poh,*pol,*pqh,*pql,*phh,*phl;
    __nv_bfloat16 *wqh,*wql,*wkh,*wkl,*wvh,*wvl,*w1h,*w1l,*w2h,*w2l;
    cudaGetSymbolAddress((void**)&pxh,  g_x_h);   cudaGetSymbolAddress((void**)&pxl,  g_x_l);
    cudaGetSymbolAddress((void**)&plih, g_xli_h); cudaGetSymbolAddress((void**)&plil, g_xli_l);
    cudaGetSymbolAddress((void**)&poh,  g_xo_h);  cudaGetSymbolAddress((void**)&pol,  g_xo_l);
    cudaGetSymbolAddress((void**)&pqh,  g_xq_h);  cudaGetSymbolAddress((void**)&pql,  g_xq_l);
    cudaGetSymbolAddress((void**)&phh,  g_hh_h);  cudaGetSymbolAddress((void**)&phl,  g_hh_l);
    cudaGetSymbolAddress((void**)&wqh,  g_wq_h);  cudaGetSymbolAddress((void**)&wql,  g_wq_l);
    cudaGetSymbolAddress((void**)&wkh,  g_wk_h);  cudaGetSymbolAddress((void**)&wkl,  g_wk_l);
    cudaGetSymbolAddress((void**)&wvh,  g_wv_h);  cudaGetSymbolAddress((void**)&wvl,  g_wv_l);
    cudaGetSymbolAddress((void**)&w1h,  g_w1_h);  cudaGetSymbolAddress((void**)&w1l,  g_w1_l);
    cudaGetSymbolAddress((void**)&w2h,  g_w2_h);  cudaGetSymbolAddress((void**)&w2l,  g_w2_l);

    cudaFuncSetAttribute(gemm_mma, cudaFuncAttributeMaxDynamicSharedMemorySize, SMEM_MMA);
    cudaFuncSetAttribute(conv_mma, cudaFuncAttributeMaxDynamicSharedMemorySize, SMEM_MMA);

    // ---- preprocessing ----
    conv_split_kernel<<<(9*DIM*DIM + 255)/256, 256>>>(convw);
    tsplit_kernel<<<(DIM*DIM)/256, 256>>>(q_w, wqh, wql, DIM, DIM);
    tsplit_kernel<<<(DIM*DIM)/256, 256>>>(k_w, wkh, wkl, DIM, DIM);
    tsplit_kernel<<<(DIM*DIM)/256, 256>>>(v_w, wvh, wvl, DIM, DIM);
    tsplit_kernel<<<(2*DIM*DIM)/256, 256>>>(w1, w1h, w1l, DIM, 2*DIM);   // -> [256,128]
    tsplit_kernel<<<(2*DIM*DIM)/256, 256>>>(w2, w2h, w2l, 2*DIM, DIM);   // -> [128,256]
    split_both_kernel<<<NROWS_IN/8, 256>>>(x, pxh, pxl, plih, plil, lin_g, lin_b);

    // k = LN_in(x) @ k_w ; v = x @ v_w
    gemm_mma<<<NROWS_IN/128, 256, SMEM_MMA>>>(plih, plil, 128, wkh, wkl,
        nullptr, nullptr, nullptr, pk, 128, nullptr, nullptr, nullptr, nullptr, 0,
        nullptr, EPI_STORE, 0);
    gemm_mma<<<NROWS_IN/128, 256, SMEM_MMA>>>(pxh, pxl, 128, wvh, wvl,
        nullptr, nullptr, nullptr, pv, 128, nullptr, nullptr, nullptr, nullptr, 0,
        nullptr, EPI_STORE, 0);
    conv_mma<<<NROWS_OUT/128, 256, SMEM_MMA>>>(lout_g, lout_b);

    for (int it = 0; it < 3; it++){
        // q = LN(x_out) @ q_w   (also zeroes colsum for the attn that follows)
        gemm_mma<<<NROWS_OUT/128, 256, SMEM_MMA>>>(pqh, pql, 128, wqh, wql,
            nullptr, nullptr, nullptr, pq, 128, nullptr, nullptr, nullptr, nullptr, 0,
            pcs, EPI_STORE, 0);
        attn_kernel<<<(BATCH*4*NPIX_OUT)/4, 128>>>(rpb, tau, out_attn);
        upd_kernel<<<NROWS_OUT/4, 128>>>(out_attn, out_acol);
        // h = gelu(x_out @ w1 + b1) -> bf16 split
        gemm_mma<<<dim3(NROWS_OUT/128, 2), 256, SMEM_MMA>>>(poh, pol, 128, w1h, w1l,
            b1, nullptr, nullptr, nullptr, 0, nullptr, nullptr, phh, phl, 256,
            nullptr, EPI_GELU, 0);
        // x_out += LN(h @ w2 + b2); xq = LN(x_out) split
        gemm_mma<<<NROWS_OUT/128, 256, SMEM_MMA>>>(phh, phl, 256, w2h, w2l,
            b2, lout_g, lout_b, nullptr, 0, pxout, out_x, pqh, pql, 128,
            nullptr, EPI_LNRES, it == 2 ? 1 : 0);
    }
    (void)in_sizes; (void)n_in; (void)out_size;
}

// round 14
// speedup vs baseline: 1.4814x; 1.0300x over previous
#include <cuda_runtime.h>
#include <cuda_bf16.h>
#include <math.h>
#include <stdint.h>

#define BATCH 4
#define HI 128
#define WI 128
#define HO 64
#define WO 64
#define DIM 128
#define NPIX_IN  (HI*WI)
#define NPIX_OUT (HO*WO)
#define NROWS_IN  (BATCH*NPIX_IN)   // 65536
#define NROWS_OUT (BATCH*NPIX_OUT)  // 16384

// ---------------- scratch (device globals) ----------------------------------
__device__ float g_k   [(size_t)NROWS_IN*DIM];
__device__ float g_v   [(size_t)NROWS_IN*DIM];
__device__ float g_q   [(size_t)NROWS_OUT*DIM];
__device__ float g_xout[(size_t)NROWS_OUT*DIM];
__device__ float g_colsum[BATCH*NPIX_OUT];

// bf16 split buffers (hi/lo)
__device__ __align__(16) __nv_bfloat16 g_x_h  [(size_t)NROWS_IN*DIM];
__device__ __align__(16) __nv_bfloat16 g_x_l  [(size_t)NROWS_IN*DIM];
__device__ __align__(16) __nv_bfloat16 g_xli_h[(size_t)NROWS_IN*DIM];   // LN_in(x)
__device__ __align__(16) __nv_bfloat16 g_xli_l[(size_t)NROWS_IN*DIM];
__device__ __align__(16) __nv_bfloat16 g_xo_h [(size_t)NROWS_OUT*DIM];  // xout (post-upd)
__device__ __align__(16) __nv_bfloat16 g_xo_l [(size_t)NROWS_OUT*DIM];
__device__ __align__(16) __nv_bfloat16 g_xq_h [(size_t)NROWS_OUT*DIM];  // LN(xout)
__device__ __align__(16) __nv_bfloat16 g_xq_l [(size_t)NROWS_OUT*DIM];
__device__ __align__(16) __nv_bfloat16 g_hh_h [(size_t)NROWS_OUT*2*DIM];
__device__ __align__(16) __nv_bfloat16 g_hh_l [(size_t)NROWS_OUT*2*DIM];
// transposed-split weights [N,K]
__device__ __align__(16) __nv_bfloat16 g_wq_h[DIM*DIM], g_wq_l[DIM*DIM];
__device__ __align__(16) __nv_bfloat16 g_wk_h[DIM*DIM], g_wk_l[DIM*DIM];
__device__ __align__(16) __nv_bfloat16 g_wv_h[DIM*DIM], g_wv_l[DIM*DIM];
__device__ __align__(16) __nv_bfloat16 g_w1_h[2*DIM*DIM], g_w1_l[2*DIM*DIM]; // [256,128]
__device__ __align__(16) __nv_bfloat16 g_w2_h[2*DIM*DIM], g_w2_l[2*DIM*DIM]; // [128,256]
// conv weights per tap: [tap][o][i] bf16 split
__device__ __align__(16) __nv_bfloat16 g_cw_h[9*DIM*DIM], g_cw_l[9*DIM*DIM];

// ---------------- helpers ----------------------------------------------------
static __device__ __forceinline__ float wredsum(float v){
#pragma unroll
    for (int o = 16; o > 0; o >>= 1) v += __shfl_xor_sync(0xffffffffu, v, o);
    return v;
}
static __device__ __forceinline__ float geluf(float x){
    return 0.5f * x * (1.0f + erff(x * 0.70710678118654752440f));
}
static __device__ __forceinline__ uint32_t smem_u32(const void* p){
    uint32_t a;
    asm("{ .reg .u64 t; cvta.to.shared.u64 t, %1; cvt.u32.u64 %0, t; }" : "=r"(a) : "l"(p));
    return a;
}
static __device__ __forceinline__ void split2(float v, __nv_bfloat16& h, __nv_bfloat16& l){
    h = __float2bfloat16(v);
    l = __float2bfloat16(v - __bfloat162float(h));
}
static __device__ __forceinline__ void split_store4(
    __nv_bfloat16* ph, __nv_bfloat16* pl, const float* v)
{
    __nv_bfloat16 h[4], l[4];
#pragma unroll
    for (int i = 0; i < 4; i++) split2(v[i], h[i], l[i]);
    *reinterpret_cast<uint2*>(ph) = *reinterpret_cast<const uint2*>(h);
    *reinterpret_cast<uint2*>(pl) = *reinterpret_cast<const uint2*>(l);
}

// ---------------- mma primitives (baseline PTX: sm_80-compatible) -----------
static __device__ __forceinline__ void ldsm_x4(uint32_t* r, uint32_t addr){
    asm volatile("ldmatrix.sync.aligned.m8n8.x4.shared.b16 {%0,%1,%2,%3}, [%4];"
        : "=r"(r[0]), "=r"(r[1]), "=r"(r[2]), "=r"(r[3]) : "r"(addr));
}
static __device__ __forceinline__ void mma16816(
    float* c, const uint32_t* a, uint32_t b0, uint32_t b1)
{
    asm volatile(
        "mma.sync.aligned.m16n8k16.row.col.f32.bf16.bf16.f32 "
        "{%0,%1,%2,%3}, {%4,%5,%6,%7}, {%8,%9}, {%0,%1,%2,%3};"
        : "+f"(c[0]), "+f"(c[1]), "+f"(c[2]), "+f"(c[3])
        : "r"(a[0]), "r"(a[1]), "r"(a[2]), "r"(a[3]), "r"(b0), "r"(b1));
}

#define EPI_STORE 0
#define EPI_GELU  1
#define EPI_LNRES 2

#define TSTRIDE 72                      // bf16 elements per smem row (pad 64->72)
#define TBYTES  (128*TSTRIDE*2)         // 18432 bytes per tile
#define OFF_AH  0
#define OFF_AL  (TBYTES)
#define OFF_BH  (2*TBYTES)
#define OFF_BL  (3*TBYTES)
#define SMEM_MMA (4*TBYTES)             // 73728

// ---------------- bf16-3x tensor-core GEMM -----------------------------------
// D[128 tile, 128 tile] = A @ B^T; A[M,Ktot] hi/lo, B[N,Ktot] hi/lo (row-major).
// blockIdx.z == 1 switches to the secondary (Ah2.., C2) problem (kv merge).
__global__ void __launch_bounds__(256,2) gemm_mma(
    const __nv_bfloat16* __restrict__ Ah, const __nv_bfloat16* __restrict__ Al, int Ktot,
    const __nv_bfloat16* __restrict__ Bh, const __nv_bfloat16* __restrict__ Bl,
    const float* __restrict__ bias,
    const float* __restrict__ lng, const float* __restrict__ lnb,
    float* __restrict__ C, int ldc,
    float* __restrict__ res, float* __restrict__ fin,
    __nv_bfloat16* __restrict__ ohi, __nv_bfloat16* __restrict__ olo, int ldo,
    float* __restrict__ zbuf,
    const __nv_bfloat16* Ah2, const __nv_bfloat16* Al2,
    const __nv_bfloat16* Bh2, const __nv_bfloat16* Bl2, float* C2,
    int epi, int writeFinal)
{
    extern __shared__ char sm[];
    const uint32_t smb = smem_u32(sm);
    const int tid = threadIdx.x, wid = tid >> 5, lane = tid & 31;
    const int wm = wid & 3, wn = wid >> 2;
    const int mBase = blockIdx.x * 128;
    const int col0  = blockIdx.y * 128;

    if (blockIdx.z == 1){
        Ah = Ah2; Al = Al2; Bh = Bh2; Bl = Bl2; C = C2;
    }

    if (zbuf != nullptr && blockIdx.y == 0 && tid < 128)
        zbuf[(size_t)blockIdx.x*128 + tid] = 0.f;

    float acc[2][8][4];
#pragma unroll
    for (int mt = 0; mt < 2; mt++)
#pragma unroll
        for (int nt = 0; nt < 8; nt++)
#pragma unroll
            for (int i = 0; i < 4; i++) acc[mt][nt][i] = 0.f;

    const __nv_bfloat16* Ah0 = Ah + (size_t)mBase*Ktot;
    const __nv_bfloat16* Al0 = Al + (size_t)mBase*Ktot;
    const __nv_bfloat16* Bh0 = Bh + (size_t)col0*Ktot;
    const __nv_bfloat16* Bl0 = Bl + (size_t)col0*Ktot;

    const int aRow = lane & 15, aKh = (lane >> 4) << 3;
    const int bRow = (lane & 7) + ((lane >> 4) << 3);
    const int bKh  = ((lane >> 3) & 1) << 3;

    for (int kc = 0; kc < Ktot; kc += 64){
        __syncthreads();
#pragma unroll
        for (int i = 0; i < 4; i++){
            int u = tid + i*256;
            int m = u >> 3, c8 = (u & 7) << 3;
            size_t go = (size_t)m*Ktot + kc + c8;
            int so = (m*TSTRIDE + c8) << 1;
            *reinterpret_cast<uint4*>(sm + OFF_AH + so) = *reinterpret_cast<const uint4*>(Ah0 + go);
            *reinterpret_cast<uint4*>(sm + OFF_AL + so) = *reinterpret_cast<const uint4*>(Al0 + go);
            *reinterpret_cast<uint4*>(sm + OFF_BH + so) = *reinterpret_cast<const uint4*>(Bh0 + go);
            *reinterpret_cast<uint4*>(sm + OFF_BL + so) = *reinterpret_cast<const uint4*>(Bl0 + go);
        }
        __syncthreads();

#pragma unroll
        for (int ks = 0; ks < 4; ks++){
            uint32_t ah[2][4], al[2][4];
#pragma unroll
            for (int mt = 0; mt < 2; mt++){
                const int eoff = ((wm*32 + mt*16 + aRow)*TSTRIDE + ks*16 + aKh) << 1;
                ldsm_x4(ah[mt], smb + OFF_AH + eoff);
                ldsm_x4(al[mt], smb + OFF_AL + eoff);
            }
#pragma unroll
            for (int np = 0; np < 4; np++){
                const int eoff = ((wn*64 + np*16 + bRow)*TSTRIDE + ks*16 + bKh) << 1;
                uint32_t bh4[4], bl4[4];
                ldsm_x4(bh4, smb + OFF_BH + eoff);
                ldsm_x4(bl4, smb + OFF_BL + eoff);
#pragma unroll
                for (int mt = 0; mt < 2; mt++){
#pragma unroll
                    for (int hf = 0; hf < 2; hf++){
                        float* c = acc[mt][np*2 + hf];
                        mma16816(c, ah[mt], bh4[hf*2], bh4[hf*2+1]);
                        mma16816(c, al[mt], bh4[hf*2], bh4[hf*2+1]);
                        mma16816(c, ah[mt], bl4[hf*2], bl4[hf*2+1]);
                    }
                }
            }
        }
    }

    // ---------------- epilogues ----------------
    if (epi == EPI_STORE){
#pragma unroll
        for (int mt = 0; mt < 2; mt++){
            const int row = mBase + wm*32 + mt*16 + (lane >> 2);
#pragma unroll
            for (int nt = 0; nt < 8; nt++){
                const int colg = col0 + wn*64 + nt*8 + ((lane & 3) << 1);
                *reinterpret_cast<float2*>(C + (size_t)row*ldc + colg) =
                    make_float2(acc[mt][nt][0], acc[mt][nt][1]);
                *reinterpret_cast<float2*>(C + (size_t)(row+8)*ldc + colg) =
                    make_float2(acc[mt][nt][2], acc[mt][nt][3]);
            }
        }
    } else if (epi == EPI_GELU){
#pragma unroll
        for (int mt = 0; mt < 2; mt++){
            const int row = mBase + wm*32 + mt*16 + (lane >> 2);
#pragma unroll
            for (int nt = 0; nt < 8; nt++){
                const int colg = col0 + wn*64 + nt*8 + ((lane & 3) << 1);
                const float b0 = bias[colg], b1 = bias[colg+1];
                float v0 = geluf(acc[mt][nt][0] + b0);
                float v1 = geluf(acc[mt][nt][1] + b1);
                float v2 = geluf(acc[mt][nt][2] + b0);
                float v3 = geluf(acc[mt][nt][3] + b1);
                __nv_bfloat16 h0,l0,h1,l1;
                split2(v0,h0,l0); split2(v1,h1,l1);
                *reinterpret_cast<__nv_bfloat162*>(ohi + (size_t)row*ldo + colg) = {h0,h1};
                *reinterpret_cast<__nv_bfloat162*>(olo + (size_t)row*ldo + colg) = {l0,l1};
                split2(v2,h0,l0); split2(v3,h1,l1);
                *reinterpret_cast<__nv_bfloat162*>(ohi + (size_t)(row+8)*ldo + colg) = {h0,h1};
                *reinterpret_cast<__nv_bfloat162*>(olo + (size_t)(row+8)*ldo + colg) = {l0,l1};
            }
        }
    } else { // EPI_LNRES
        __syncthreads();
        float* sf = reinterpret_cast<float*>(sm);
#pragma unroll
        for (int mt = 0; mt < 2; mt++){
            const int lr = wm*32 + mt*16 + (lane >> 2);
#pragma unroll
            for (int nt = 0; nt < 8; nt++){
                const int lc = wn*64 + nt*8 + ((lane & 3) << 1);
                const float b0 = bias[lc], b1 = bias[lc+1];
                sf[lr*132 + lc]       = acc[mt][nt][0] + b0;
                sf[lr*132 + lc + 1]   = acc[mt][nt][1] + b1;
                sf[(lr+8)*132 + lc]   = acc[mt][nt][2] + b0;
                sf[(lr+8)*132 + lc+1] = acc[mt][nt][3] + b1;
            }
        }
        __syncthreads();
        const float4 gg = reinterpret_cast<const float4*>(lng)[lane];
        const float4 lb = reinterpret_cast<const float4*>(lnb)[lane];
        for (int r = wid*16; r < wid*16 + 16; r++){
            float4 v = *reinterpret_cast<float4*>(sf + r*132 + lane*4);
            float mu = wredsum(v.x+v.y+v.z+v.w) * (1.0f/128.0f);
            float dx=v.x-mu, dy=v.y-mu, dz=v.z-mu, dw=v.w-mu;
            float var = wredsum(dx*dx+dy*dy+dz*dz+dw*dw) * (1.0f/128.0f);
            float rs = rsqrtf(var + 1e-5f);
            const int row = mBase + r;
            float* rp = res + (size_t)row*DIM;
            float4 r4 = reinterpret_cast<float4*>(rp)[lane];
            float o[4];
            o[0] = r4.x + dx*rs*gg.x + lb.x;
            o[1] = r4.y + dy*rs*gg.y + lb.y;
            o[2] = r4.z + dz*rs*gg.z + lb.z;
            o[3] = r4.w + dw*rs*gg.w + lb.w;
            float4 o4 = make_float4(o[0],o[1],o[2],o[3]);
            reinterpret_cast<float4*>(rp)[lane] = o4;
            if (writeFinal)
                reinterpret_cast<float4*>(fin + (size_t)row*DIM)[lane] = o4;
            float mu2 = wredsum(o[0]+o[1]+o[2]+o[3]) * (1.0f/128.0f);
            float e0=o[0]-mu2, e1=o[1]-mu2, e2=o[2]-mu2, e3=o[3]-mu2;
            float var2 = wredsum(e0*e0+e1*e1+e2*e2+e3*e3) * (1.0f/128.0f);
            float rs2 = rsqrtf(var2 + 1e-5f);
            float x2[4];
            x2[0] = e0*rs2*gg.x + lb.x; x2[1] = e1*rs2*gg.y + lb.y;
            x2[2] = e2*rs2*gg.z + lb.z; x2[3] = e3*rs2*gg.w + lb.w;
            split_store4(ohi + (size_t)row*DIM + lane*4,
                         olo + (size_t)row*DIM + lane*4, x2);
        }
    }
}

// ---------------- conv as implicit tensor-core GEMM --------------------------
__global__ void __launch_bounds__(256) conv_mma(
    const float* __restrict__ lng, const float* __restrict__ lnb)
{
    extern __shared__ char sm[];
    const uint32_t smb = smem_u32(sm);
    const int tid = threadIdx.x, wid = tid >> 5, lane = tid & 31;
    const int wm = wid & 3, wn = wid >> 2;
    const int mBase = blockIdx.x * 128;

    float acc[2][8][4];
#pragma unroll
    for (int mt = 0; mt < 2; mt++)
#pragma unroll
        for (int nt = 0; nt < 8; nt++)
#pragma unroll
            for (int i = 0; i < 4; i++) acc[mt][nt][i] = 0.f;

    const int aRow = lane & 15, aKh = (lane >> 4) << 3;
    const int bRow = (lane & 7) + ((lane >> 4) << 3);
    const int bKh  = ((lane >> 3) & 1) << 3;

    for (int tap = 0; tap < 9; tap++){
        const int kh = tap/3 - 1, kw = tap%3 - 1;
        for (int kc = 0; kc < 2; kc++){
            __syncthreads();
#pragma unroll
            for (int i = 0; i < 4; i++){
                int u = tid + i*256;
                int m = u >> 3, c8 = (u & 7) << 3;
                const int p = mBase + m;
                const int b = p >> 12, hw = p & 4095;
                const int h = hw >> 6, w = hw & 63;
                const int hi = 2*h + kh, wi = 2*w + kw;
                uint4 vh = make_uint4(0,0,0,0), vl = make_uint4(0,0,0,0);
                if ((unsigned)hi < HI && (unsigned)wi < WI){
                    size_t go = ((size_t)b*NPIX_IN + hi*WI + wi)*DIM + kc*64 + c8;
                    vh = *reinterpret_cast<const uint4*>(g_x_h + go);
                    vl = *reinterpret_cast<const uint4*>(g_x_l + go);
                }
                int so = (m*TSTRIDE + c8) << 1;
                *reinterpret_cast<uint4*>(sm + OFF_AH + so) = vh;
                *reinterpret_cast<uint4*>(sm + OFF_AL + so) = vl;
                size_t gb = (size_t)tap*DIM*DIM + (size_t)m*DIM + kc*64 + c8;
                *reinterpret_cast<uint4*>(sm + OFF_BH + so) =
                    *reinterpret_cast<const uint4*>(g_cw_h + gb);
                *reinterpret_cast<uint4*>(sm + OFF_BL + so) =
                    *reinterpret_cast<const uint4*>(g_cw_l + gb);
            }
            __syncthreads();
#pragma unroll
            for (int ks = 0; ks < 4; ks++){
                uint32_t ah[2][4], al[2][4];
#pragma unroll
                for (int mt = 0; mt < 2; mt++){
                    const int eoff = ((wm*32 + mt*16 + aRow)*TSTRIDE + ks*16 + aKh) << 1;
                    ldsm_x4(ah[mt], smb + OFF_AH + eoff);
                    ldsm_x4(al[mt], smb + OFF_AL + eoff);
                }
#pragma unroll
                for (int np = 0; np < 4; np++){
                    const int eoff = ((wn*64 + np*16 + bRow)*TSTRIDE + ks*16 + bKh) << 1;
                    uint32_t bh4[4], bl4[4];
                    ldsm_x4(bh4, smb + OFF_BH + eoff);
                    ldsm_x4(bl4, smb + OFF_BL + eoff);
#pragma unroll
                    for (int mt = 0; mt < 2; mt++){
#pragma unroll
                        for (int hf = 0; hf < 2; hf++){
                            float* c = acc[mt][np*2 + hf];
                            mma16816(c, ah[mt], bh4[hf*2], bh4[hf*2+1]);
                            mma16816(c, al[mt], bh4[hf*2], bh4[hf*2+1]);
                            mma16816(c, ah[mt], bl4[hf*2], bl4[hf*2+1]);
                        }
                    }
                }
            }
        }
    }

    __syncthreads();
    float* sf = reinterpret_cast<float*>(sm);
#pragma unroll
    for (int mt = 0; mt < 2; mt++){
        const int lr = wm*32 + mt*16 + (lane >> 2);
#pragma unroll
        for (int nt = 0; nt < 8; nt++){
            const int lc = wn*64 + nt*8 + ((lane & 3) << 1);
            sf[lr*132 + lc]       = acc[mt][nt][0];
            sf[lr*132 + lc + 1]   = acc[mt][nt][1];
            sf[(lr+8)*132 + lc]   = acc[mt][nt][2];
            sf[(lr+8)*132 + lc+1] = acc[mt][nt][3];
        }
    }
    __syncthreads();
    const float4 gg = reinterpret_cast<const float4*>(lng)[lane];
    const float4 lb = reinterpret_cast<const float4*>(lnb)[lane];
    for (int r = wid*16; r < wid*16 + 16; r++){
        float4 v = *reinterpret_cast<float4*>(sf + r*132 + lane*4);
        float mu = wredsum(v.x+v.y+v.z+v.w) * (1.0f/128.0f);
        float dx=v.x-mu, dy=v.y-mu, dz=v.z-mu, dw=v.w-mu;
        float var = wredsum(dx*dx+dy*dy+dz*dz+dw*dw) * (1.0f/128.0f);
        float rs = rsqrtf(var + 1e-5f);
        const int row = mBase + r;
        float o[4];
        o[0] = dx*rs*gg.x + lb.x; o[1] = dy*rs*gg.y + lb.y;
        o[2] = dz*rs*gg.z + lb.z; o[3] = dw*rs*gg.w + lb.w;
        reinterpret_cast<float4*>(g_xout + (size_t)row*DIM)[lane] =
            make_float4(o[0],o[1],o[2],o[3]);
        float mu2 = wredsum(o[0]+o[1]+o[2]+o[3]) * (1.0f/128.0f);
        float e0=o[0]-mu2, e1=o[1]-mu2, e2=o[2]-mu2, e3=o[3]-mu2;
        float var2 = wredsum(e0*e0+e1*e1+e2*e2+e3*e3) * (1.0f/128.0f);
        float rs2 = rsqrtf(var2 + 1e-5f);
        float x2[4];
        x2[0] = e0*rs2*gg.x + lb.x; x2[1] = e1*rs2*gg.y + lb.y;
        x2[2] = e2*rs2*gg.z + lb.z; x2[3] = e3*rs2*gg.w + lb.w;
        split_store4(g_xq_h + (size_t)row*DIM + lane*4,
                     g_xq_l + (size_t)row*DIM + lane*4, x2);
    }
}

// ---------------- unified preprocessing kernel -------------------------------
// blocks [0, 8192):    row split of x -> (x_h,x_l) and LN_in(x) -> (xli_h,xli_l)
// blocks [8192, 9216): all weight transposes/splits (262144 elements)
#define PREP_ROW_BLOCKS (NROWS_IN/8)    // 8192
__global__ void __launch_bounds__(256) prep_kernel(
    const float* __restrict__ x,
    const float* __restrict__ convw,
    const float* __restrict__ q_w, const float* __restrict__ k_w,
    const float* __restrict__ v_w,
    const float* __restrict__ w1, const float* __restrict__ w2,
    const float* __restrict__ lin_g, const float* __restrict__ lin_b)
{
    if (blockIdx.x < PREP_ROW_BLOCKS){
        const int lane = threadIdx.x & 31, warp = threadIdx.x >> 5;
        const size_t row = (size_t)blockIdx.x*8 + warp;
        float4 v = reinterpret_cast<const float4*>(x + row*DIM)[lane];
        float t[4] = {v.x, v.y, v.z, v.w};
        split_store4(g_x_h + row*DIM + lane*4, g_x_l + row*DIM + lane*4, t);
        float mu = wredsum(v.x+v.y+v.z+v.w) * (1.0f/DIM);
        float dx=v.x-mu, dy=v.y-mu, dz=v.z-mu, dw=v.w-mu;
        float var = wredsum(dx*dx+dy*dy+dz*dz+dw*dw) * (1.0f/DIM);
        float rs = rsqrtf(var + 1e-5f);
        float4 gg = reinterpret_cast<const float4*>(lin_g)[lane];
        float4 bb = reinterpret_cast<const float4*>(lin_b)[lane];
        float u[4];
        u[0] = dx*rs*gg.x + bb.x; u[1] = dy*rs*gg.y + bb.y;
        u[2] = dz*rs*gg.z + bb.z; u[3] = dw*rs*gg.w + bb.w;
        split_store4(g_xli_h + row*DIM + lane*4, g_xli_l + row*DIM + lane*4, u);
        return;
    }
    int idx = (blockIdx.x - PREP_ROW_BLOCKS)*256 + threadIdx.x;  // [0, 262144)
    __nv_bfloat16 h, l;
    if (idx < 16384){                       // q_w [128,128] -> [N,K]
        int k = idx >> 7, n = idx & 127;
        split2(q_w[idx], h, l);
        g_wq_h[n*DIM + k] = h; g_wq_l[n*DIM + k] = l;
    } else if (idx < 32768){                // k_w
        int i = idx - 16384;
        int k = i >> 7, n = i & 127;
        split2(k_w[i], h, l);
        g_wk_h[n*DIM + k] = h; g_wk_l[n*DIM + k] = l;
    } else if (idx < 49152){                // v_w
        int i = idx - 32768;
        int k = i >> 7, n = i & 127;
        split2(v_w[i], h, l);
        g_wv_h[n*DIM + k] = h; g_wv_l[n*DIM + k] = l;
    } else if (idx < 81920){                // w1 [128,256] -> [256,128]
        int i = idx - 49152;
        int k = i >> 8, n = i & 255;
        split2(w1[i], h, l);
        g_w1_h[(size_t)n*DIM + k] = h; g_w1_l[(size_t)n*DIM + k] = l;
    } else if (idx < 114688){               // w2 [256,128] -> [128,256]
        int i = idx - 81920;
        int k = i >> 7, n = i & 127;
        split2(w2[i], h, l);
        g_w2_h[(size_t)n*256 + k] = h; g_w2_l[(size_t)n*256 + k] = l;
    } else {                                // convw [o][i][tap] -> [tap][o][i]
        int i = idx - 114688;               // [0, 147456)
        int o   = i / (DIM*9);
        int rem = i - o*(DIM*9);
        int ii  = rem / 9;
        int tap = rem - ii*9;
        split2(convw[i], h, l);
        g_cw_h[(size_t)tap*DIM*DIM + o*DIM + ii] = h;
        g_cw_l[(size_t)tap*DIM*DIM + o*DIM + ii] = l;
    }
}

// ---------------- attention: scores + softmax + eps + colsum atomics ---------
__global__ void attn_kernel(const float* __restrict__ rpb,
                            const float* __restrict__ tau,
                            float* __restrict__ attn_out)
{
    const int tid = threadIdx.x, warp = tid >> 5, lane = tid & 31;
    const int id  = blockIdx.x*4 + warp;
    const int b   = id >> 14;
    const int rem = id & 16383;
    const int g   = rem >> 12;
    const int hw  = rem & 4095;
    const int h = hw >> 6, w = hw & 63;
    const int ga = g >> 1, gb = g & 1;
    const int pix = (2*h + ga)*WI + 2*w + gb;
    const float4 kv = reinterpret_cast<const float4*>(g_k + ((size_t)b*NPIX_IN + pix)*DIM)[lane];
    const float scale = expf(tau[0]);
    const int ch = min(max(h,1), HO-2), cw = min(max(w,1), WO-2);

    float p[9];
    float m = -1e30f;
#pragma unroll
    for (int t = 0; t < 9; t++){
        const int nh = ch + t/3 - 1, nw = cw + t%3 - 1;
        const float4 q4 = reinterpret_cast<const float4*>(g_q + ((size_t)b*NPIX_OUT + nh*WO + nw)*DIM)[lane];
        float d = kv.x*q4.x + kv.y*q4.y + kv.z*q4.z + kv.w*q4.w;
        d = wredsum(d);
        const float val = (d + rpb[g*9 + t]) * scale;
        p[t] = val;
        m = fmaxf(m, val);
    }
    float s = 0.f;
#pragma unroll
    for (int t = 0; t < 9; t++){ p[t] = expf(p[t] - m); s += p[t]; }
    const float inv = 1.f/s;
#pragma unroll
    for (int t = 0; t < 9; t++) p[t] = p[t]*inv + 1e-6f;

    if (lane == 0){
        float* ao = attn_out + (size_t)id*9;
#pragma unroll
        for (int t = 0; t < 9; t++) ao[t] = p[t];
#pragma unroll
        for (int t = 0; t < 9; t++){
            const int nh = ch + t/3 - 1, nw = cw + t%3 - 1;
            atomicAdd(&g_colsum[b*NPIX_OUT + nh*WO + nw], p[t]);
        }
    }
}

// ---------------- aggregation: A_col + upd + residual + xout split -----------
__global__ void upd_kernel(const float* __restrict__ attn_in,
                           float* __restrict__ acol_out)
{
    const int tid = threadIdx.x, warp = tid >> 5, lane = tid & 31;
    const int id = blockIdx.x*4 + warp;
    const int b  = id >> 12;
    const int hw = id & 4095;
    const int h = hw >> 6, w = hw & 63;
    const int ch = min(max(h,1), HO-2), cw = min(max(w,1), WO-2);

    float inv_dn[9];
#pragma unroll
    for (int t = 0; t < 9; t++){
        const int nh = ch + t/3 - 1, nw = cw + t%3 - 1;
        inv_dn[t] = 1.0f / (g_colsum[b*NPIX_OUT + nh*WO + nw] + 1e-8f);
    }
    float4 acc = make_float4(0.f,0.f,0.f,0.f);
#pragma unroll
    for (int g = 0; g < 4; g++){
        const int ga = g >> 1, gb = g & 1;
        const size_t base = ((size_t)((b*4 + g)*NPIX_OUT) + hw)*9;
        const float* ab = attn_in + base;
        float* cb = acol_out + base;
#pragma unroll
        for (int t = 0; t < 9; t++){
            const float coeff = ab[t] * inv_dn[t];
            if (lane == 0) cb[t] = coeff;
            const int nh = ch + t/3 - 1, nw = cw + t%3 - 1;
            const int pix = (2*nh + ga)*WI + 2*nw + gb;
            const float4 vv = reinterpret_cast<const float4*>(g_v + ((size_t)b*NPIX_IN + pix)*DIM)[lane];
            acc.x += coeff*vv.x; acc.y += coeff*vv.y; acc.z += coeff*vv.z; acc.w += coeff*vv.w;
        }
    }
    float4* xo = reinterpret_cast<float4*>(g_xout + (size_t)id*DIM);
    float4 v = xo[lane];
    v.x += acc.x; v.y += acc.y; v.z += acc.z; v.w += acc.w;
    xo[lane] = v;
    float t4[4] = {v.x, v.y, v.z, v.w};
    split_store4(g_xo_h + (size_t)id*DIM + lane*4,
                 g_xo_l + (size_t)id*DIM + lane*4, t4);
}

// ---------------- launch ------------------------------------------------------
extern "C" void kernel_launch(void* const* d_in, const int* in_sizes, int n_in,
                              void* d_out, int out_size)
{
    const float* x      = (const float*)d_in[0];
    const float* convw  = (const float*)d_in[1];
    const float* q_w    = (const float*)d_in[2];
    const float* k_w    = (const float*)d_in[3];
    const float* v_w    = (const float*)d_in[4];
    const float* w1     = (const float*)d_in[5];
    const float* b1     = (const float*)d_in[6];
    const float* w2     = (const float*)d_in[7];
    const float* b2     = (const float*)d_in[8];
    const float* lin_g  = (const float*)d_in[9];
    const float* lin_b  = (const float*)d_in[10];
    const float* lout_g = (const float*)d_in[11];
    const float* lout_b = (const float*)d_in[12];
    const float* tau    = (const float*)d_in[13];
    const float* rpb    = (const float*)d_in[14];

    float* out      = (float*)d_out;
    float* out_x    = out;
    float* out_attn = out + (size_t)NROWS_OUT*DIM;
    float* out_acol = out_attn + (size_t)BATCH*4*NPIX_OUT*9;

    float *pk, *pv, *pq, *pxout, *pcs;
    cudaGetSymbolAddress((void**)&pk,    g_k);
    cudaGetSymbolAddress((void**)&pv,    g_v);
    cudaGetSymbolAddress((void**)&pq,    g_q);
    cudaGetSymbolAddress((void**)&pxout, g_xout);
    cudaGetSymbolAddress((void**)&pcs,   g_colsum);
    __nv_bfloat16 *pxh,*pxl,*plih,*plil,*poh,*pol,*pqh,*pql,*phh,*phl;
    __nv_bfloat16 *wqh,*wql,*wkh,*wkl,*wvh,*wvl,*w1h,*w1l,*w2h,*w2l;
    cudaGetSymbolAddress((void**)&pxh,  g_x_h);   cudaGetSymbolAddress((void**)&pxl,  g_x_l);
    cudaGetSymbolAddress((void**)&plih, g_xli_h); cudaGetSymbolAddress((void**)&plil, g_xli_l);
    cudaGetSymbolAddress((void**)&poh,  g_xo_h);  cudaGetSymbolAddress((void**)&pol,  g_xo_l);
    cudaGetSymbolAddress((void**)&pqh,  g_xq_h);  cudaGetSymbolAddress((void**)&pql,  g_xq_l);
    cudaGetSymbolAddress((void**)&phh,  g_hh_h);  cudaGetSymbolAddress((void**)&phl,  g_hh_l);
    cudaGetSymbolAddress((void**)&wqh,  g_wq_h);  cudaGetSymbolAddress((void**)&wql,  g_wq_l);
    cudaGetSymbolAddress((void**)&wkh,  g_wk_h);  cudaGetSymbolAddress((void**)&wkl,  g_wk_l);
    cudaGetSymbolAddress((void**)&wvh,  g_wv_h);  cudaGetSymbolAddress((void**)&wvl,  g_wv_l);
    cudaGetSymbolAddress((void**)&w1h,  g_w1_h);  cudaGetSymbolAddress((void**)&w1l,  g_w1_l);
    cudaGetSymbolAddress((void**)&w2h,  g_w2_h);  cudaGetSymbolAddress((void**)&w2l,  g_w2_l);

    cudaFuncSetAttribute(gemm_mma, cudaFuncAttributeMaxDynamicSharedMemorySize, SMEM_MMA);
    cudaFuncSetAttribute(conv_mma, cudaFuncAttributeMaxDynamicSharedMemorySize, SMEM_MMA);

    // ---- preprocessing: single kernel (row splits + all weight splits) ----
    prep_kernel<<<PREP_ROW_BLOCKS + 1024, 256>>>(
        x, convw, q_w, k_w, v_w, w1, w2, lin_g, lin_b);

    // k = LN_in(x) @ k_w  AND  v = x @ v_w  in one launch (z = 0 / 1)
    gemm_mma<<<dim3(NROWS_IN/128, 1, 2), 256, SMEM_MMA>>>(
        plih, plil, 128, wkh, wkl,
        nullptr, nullptr, nullptr, pk, 128, nullptr, nullptr, nullptr, nullptr, 0,
        nullptr, pxh, pxl, wvh, wvl, pv,
        EPI_STORE, 0);
    conv_mma<<<NROWS_OUT/128, 256, SMEM_MMA>>>(lout_g, lout_b);

    for (int it = 0; it < 3; it++){
        // q = LN(x_out) @ q_w   (also zeroes colsum for the attn that follows)
        gemm_mma<<<NROWS_OUT/128, 256, SMEM_MMA>>>(pqh, pql, 128, wqh, wql,
            nullptr, nullptr, nullptr, pq, 128, nullptr, nullptr, nullptr, nullptr, 0,
            pcs, nullptr, nullptr, nullptr, nullptr, nullptr,
            EPI_STORE, 0);
        attn_kernel<<<(BATCH*4*NPIX_OUT)/4, 128>>>(rpb, tau, out_attn);
        upd_kernel<<<NROWS_OUT/4, 128>>>(out_attn, out_acol);
        // h = gelu(x_out @ w1 + b1) -> bf16 split
        gemm_mma<<<dim3(NROWS_OUT/128, 2), 256, SMEM_MMA>>>(poh, pol, 128, w1h, w1l,
            b1, nullptr, nullptr, nullptr, 0, nullptr, nullptr, phh, phl, 256,
            nullptr, nullptr, nullptr, nullptr, nullptr, nullptr,
            EPI_GELU, 0);
        // x_out += LN(h @ w2 + b2); xq = LN(x_out) split
        gemm_mma<<<NROWS_OUT/128, 256, SMEM_MMA>>>(phh, phl, 256, w2h, w2l,
            b2, lout_g, lout_b, nullptr, 0, pxout, out_x, pqh, pql, 128,
            nullptr, nullptr, nullptr, nullptr, nullptr, nullptr,
            EPI_LNRES, it == 2 ? 1 : 0);
    }
    (void)in_sizes; (void)n_in; (void)out_size;
}

// round 15
// speedup vs baseline: 1.5598x; 1.0529x over previous
#include <cuda_runtime.h>
#include <cuda_bf16.h>
#include <math.h>
#include <stdint.h>

#define BATCH 4
#define HI 128
#define WI 128
#define HO 64
#define WO 64
#define DIM 128
#define NPIX_IN  (HI*WI)
#define NPIX_OUT (HO*WO)
#define NROWS_IN  (BATCH*NPIX_IN)   // 65536
#define NROWS_OUT (BATCH*NPIX_OUT)  // 16384

// ---------------- scratch (device globals) ----------------------------------
__device__ float g_k   [(size_t)NROWS_IN*DIM];
__device__ float g_v   [(size_t)NROWS_IN*DIM];
__device__ float g_q   [(size_t)NROWS_OUT*DIM];
__device__ float g_xout[(size_t)NROWS_OUT*DIM];
__device__ float g_colsum[BATCH*NPIX_OUT];

// bf16 split buffers (hi/lo)
__device__ __align__(16) __nv_bfloat16 g_x_h  [(size_t)NROWS_IN*DIM];
__device__ __align__(16) __nv_bfloat16 g_x_l  [(size_t)NROWS_IN*DIM];
__device__ __align__(16) __nv_bfloat16 g_xli_h[(size_t)NROWS_IN*DIM];   // LN_in(x)
__device__ __align__(16) __nv_bfloat16 g_xli_l[(size_t)NROWS_IN*DIM];
__device__ __align__(16) __nv_bfloat16 g_xo_h [(size_t)NROWS_OUT*DIM];  // xout (post-upd)
__device__ __align__(16) __nv_bfloat16 g_xo_l [(size_t)NROWS_OUT*DIM];
__device__ __align__(16) __nv_bfloat16 g_xq_h [(size_t)NROWS_OUT*DIM];  // LN(xout)
__device__ __align__(16) __nv_bfloat16 g_xq_l [(size_t)NROWS_OUT*DIM];
__device__ __align__(16) __nv_bfloat16 g_hh_h [(size_t)NROWS_OUT*2*DIM];
__device__ __align__(16) __nv_bfloat16 g_hh_l [(size_t)NROWS_OUT*2*DIM];
// transposed-split weights [N,K]
__device__ __align__(16) __nv_bfloat16 g_wq_h[DIM*DIM], g_wq_l[DIM*DIM];
__device__ __align__(16) __nv_bfloat16 g_wk_h[DIM*DIM], g_wk_l[DIM*DIM];
__device__ __align__(16) __nv_bfloat16 g_wv_h[DIM*DIM], g_wv_l[DIM*DIM];
__device__ __align__(16) __nv_bfloat16 g_w1_h[2*DIM*DIM], g_w1_l[2*DIM*DIM]; // [256,128]
__device__ __align__(16) __nv_bfloat16 g_w2_h[2*DIM*DIM], g_w2_l[2*DIM*DIM]; // [128,256]
// conv weights per tap: [tap][o][i] bf16 split
__device__ __align__(16) __nv_bfloat16 g_cw_h[9*DIM*DIM], g_cw_l[9*DIM*DIM];

// ---------------- helpers ----------------------------------------------------
static __device__ __forceinline__ float wredsum(float v){
#pragma unroll
    for (int o = 16; o > 0; o >>= 1) v += __shfl_xor_sync(0xffffffffu, v, o);
    return v;
}
static __device__ __forceinline__ float geluf(float x){
    return 0.5f * x * (1.0f + erff(x * 0.70710678118654752440f));
}
static __device__ __forceinline__ uint32_t smem_u32(const void* p){
    uint32_t a;
    asm("{ .reg .u64 t; cvta.to.shared.u64 t, %1; cvt.u32.u64 %0, t; }" : "=r"(a) : "l"(p));
    return a;
}
static __device__ __forceinline__ void split2(float v, __nv_bfloat16& h, __nv_bfloat16& l){
    h = __float2bfloat16(v);
    l = __float2bfloat16(v - __bfloat162float(h));
}
static __device__ __forceinline__ void split_store4(
    __nv_bfloat16* ph, __nv_bfloat16* pl, const float* v)
{
    __nv_bfloat16 h[4], l[4];
#pragma unroll
    for (int i = 0; i < 4; i++) split2(v[i], h[i], l[i]);
    *reinterpret_cast<uint2*>(ph) = *reinterpret_cast<const uint2*>(h);
    *reinterpret_cast<uint2*>(pl) = *reinterpret_cast<const uint2*>(l);
}
static __device__ __forceinline__ void cp16(void* dst, const void* src){
    unsigned s = (unsigned)__cvta_generic_to_shared(dst);
    asm volatile("cp.async.cg.shared.global [%0], [%1], 16;" :: "r"(s), "l"(src));
}
static __device__ __forceinline__ void cp_commit(){
    asm volatile("cp.async.commit_group;");
}
template<int N>
static __device__ __forceinline__ void cp_wait(){
    asm volatile("cp.async.wait_group %0;" :: "n"(N));
}

// ---------------- mma primitives (baseline PTX: sm_80-compatible) -----------
static __device__ __forceinline__ void ldsm_x4(uint32_t* r, uint32_t addr){
    asm volatile("ldmatrix.sync.aligned.m8n8.x4.shared.b16 {%0,%1,%2,%3}, [%4];"
        : "=r"(r[0]), "=r"(r[1]), "=r"(r[2]), "=r"(r[3]) : "r"(addr));
}
static __device__ __forceinline__ void mma16816(
    float* c, const uint32_t* a, uint32_t b0, uint32_t b1)
{
    asm volatile(
        "mma.sync.aligned.m16n8k16.row.col.f32.bf16.bf16.f32 "
        "{%0,%1,%2,%3}, {%4,%5,%6,%7}, {%8,%9}, {%0,%1,%2,%3};"
        : "+f"(c[0]), "+f"(c[1]), "+f"(c[2]), "+f"(c[3])
        : "r"(a[0]), "r"(a[1]), "r"(a[2]), "r"(a[3]), "r"(b0), "r"(b1));
}

#define EPI_STORE 0
#define EPI_GELU  1
#define EPI_LNRES 2

// BK=32 chunking, 2-stage cp.async pipeline
#define TS2 40                          // bf16 per smem row (pad 32->40)
#define TILEB (128*TS2*2)               // 10240 bytes per tile
#define STAGEB (4*TILEB)                // 40960 per stage (AH,AL,BH,BL)
#define OFF_AH 0
#define OFF_AL TILEB
#define OFF_BH (2*TILEB)
#define OFF_BL (3*TILEB)
#define SMEM_MMA (2*STAGEB)             // 81920

// ---------------- bf16-3x tensor-core GEMM (pipelined) -----------------------
// D[128 tile, 128 tile] = A @ B^T; A[M,Ktot] hi/lo, B[N,Ktot] hi/lo (row-major).
// blockIdx.z == 1 switches to the secondary (Ah2.., C2) problem (kv merge).
__global__ void __launch_bounds__(256,2) gemm_mma(
    const __nv_bfloat16* __restrict__ Ah, const __nv_bfloat16* __restrict__ Al, int Ktot,
    const __nv_bfloat16* __restrict__ Bh, const __nv_bfloat16* __restrict__ Bl,
    const float* __restrict__ bias,
    const float* __restrict__ lng, const float* __restrict__ lnb,
    float* __restrict__ C, int ldc,
    float* __restrict__ res, float* __restrict__ fin,
    __nv_bfloat16* __restrict__ ohi, __nv_bfloat16* __restrict__ olo, int ldo,
    float* __restrict__ zbuf,
    const __nv_bfloat16* Ah2, const __nv_bfloat16* Al2,
    const __nv_bfloat16* Bh2, const __nv_bfloat16* Bl2, float* C2,
    int epi, int writeFinal)
{
    extern __shared__ char sm[];
    const uint32_t smb = smem_u32(sm);
    const int tid = threadIdx.x, wid = tid >> 5, lane = tid & 31;
    const int wm = wid & 3, wn = wid >> 2;
    const int mBase = blockIdx.x * 128;
    const int col0  = blockIdx.y * 128;

    if (blockIdx.z == 1){
        Ah = Ah2; Al = Al2; Bh = Bh2; Bl = Bl2; C = C2;
    }

    if (zbuf != nullptr && blockIdx.y == 0 && tid < 128)
        zbuf[(size_t)blockIdx.x*128 + tid] = 0.f;

    float acc[2][8][4];
#pragma unroll
    for (int mt = 0; mt < 2; mt++)
#pragma unroll
        for (int nt = 0; nt < 8; nt++)
#pragma unroll
            for (int i = 0; i < 4; i++) acc[mt][nt][i] = 0.f;

    const __nv_bfloat16* Ah0 = Ah + (size_t)mBase*Ktot;
    const __nv_bfloat16* Al0 = Al + (size_t)mBase*Ktot;
    const __nv_bfloat16* Bh0 = Bh + (size_t)col0*Ktot;
    const __nv_bfloat16* Bl0 = Bl + (size_t)col0*Ktot;

    // load indices: 2 x 16B units per thread per array per chunk
    const int lm  = tid >> 2;            // +64 rows on second unit
    const int lc8 = (tid & 3) << 3;

    const int aRow = lane & 15, aKh = (lane >> 4) << 3;
    const int bRow = (lane & 7) + ((lane >> 4) << 3);
    const int bKh  = ((lane >> 3) & 1) << 3;

    const int nCh = Ktot >> 5;

    auto issue_chunk = [&](int ch, int stage){
        char* st = sm + stage*STAGEB;
        const int kc = ch << 5;
#pragma unroll
        for (int i = 0; i < 2; i++){
            const int m = lm + i*64;
            const size_t go = (size_t)m*Ktot + kc + lc8;
            const int so = (m*TS2 + lc8) << 1;
            cp16(st + OFF_AH + so, Ah0 + go);
            cp16(st + OFF_AL + so, Al0 + go);
            cp16(st + OFF_BH + so, Bh0 + go);
            cp16(st + OFF_BL + so, Bl0 + go);
        }
        cp_commit();
    };

    issue_chunk(0, 0);
    issue_chunk(1, 1);

    for (int c = 0; c < nCh; c++){
        if (c + 1 < nCh) cp_wait<1>(); else cp_wait<0>();
        __syncthreads();
        const char* st = sm + (c & 1)*STAGEB;
        const uint32_t stb = smb + (uint32_t)((c & 1)*STAGEB);
#pragma unroll
        for (int ks = 0; ks < 2; ks++){
            uint32_t ah[2][4], al[2][4];
#pragma unroll
            for (int mt = 0; mt < 2; mt++){
                const int eoff = ((wm*32 + mt*16 + aRow)*TS2 + ks*16 + aKh) << 1;
                ldsm_x4(ah[mt], stb + OFF_AH + eoff);
                ldsm_x4(al[mt], stb + OFF_AL + eoff);
            }
#pragma unroll
            for (int np = 0; np < 4; np++){
                const int eoff = ((wn*64 + np*16 + bRow)*TS2 + ks*16 + bKh) << 1;
                uint32_t bh4[4], bl4[4];
                ldsm_x4(bh4, stb + OFF_BH + eoff);
                ldsm_x4(bl4, stb + OFF_BL + eoff);
#pragma unroll
                for (int mt = 0; mt < 2; mt++){
#pragma unroll
                    for (int hf = 0; hf < 2; hf++){
                        float* cc = acc[mt][np*2 + hf];
                        mma16816(cc, ah[mt], bh4[hf*2], bh4[hf*2+1]);
                        mma16816(cc, al[mt], bh4[hf*2], bh4[hf*2+1]);
                        mma16816(cc, ah[mt], bl4[hf*2], bl4[hf*2+1]);
                    }
                }
            }
        }
        __syncthreads();
        if (c + 2 < nCh) issue_chunk(c + 2, c & 1);
        (void)st;
    }

    // ---------------- epilogues ----------------
    if (epi == EPI_STORE){
#pragma unroll
        for (int mt = 0; mt < 2; mt++){
            const int row = mBase + wm*32 + mt*16 + (lane >> 2);
#pragma unroll
            for (int nt = 0; nt < 8; nt++){
                const int colg = col0 + wn*64 + nt*8 + ((lane & 3) << 1);
                *reinterpret_cast<float2*>(C + (size_t)row*ldc + colg) =
                    make_float2(acc[mt][nt][0], acc[mt][nt][1]);
                *reinterpret_cast<float2*>(C + (size_t)(row+8)*ldc + colg) =
                    make_float2(acc[mt][nt][2], acc[mt][nt][3]);
            }
        }
    } else if (epi == EPI_GELU){
#pragma unroll
        for (int mt = 0; mt < 2; mt++){
            const int row = mBase + wm*32 + mt*16 + (lane >> 2);
#pragma unroll
            for (int nt = 0; nt < 8; nt++){
                const int colg = col0 + wn*64 + nt*8 + ((lane & 3) << 1);
                const float b0 = bias[colg], b1 = bias[colg+1];
                float v0 = geluf(acc[mt][nt][0] + b0);
                float v1 = geluf(acc[mt][nt][1] + b1);
                float v2 = geluf(acc[mt][nt][2] + b0);
                float v3 = geluf(acc[mt][nt][3] + b1);
                __nv_bfloat16 h0,l0,h1,l1;
                split2(v0,h0,l0); split2(v1,h1,l1);
                *reinterpret_cast<__nv_bfloat162*>(ohi + (size_t)row*ldo + colg) = {h0,h1};
                *reinterpret_cast<__nv_bfloat162*>(olo + (size_t)row*ldo + colg) = {l0,l1};
                split2(v2,h0,l0); split2(v3,h1,l1);
                *reinterpret_cast<__nv_bfloat162*>(ohi + (size_t)(row+8)*ldo + colg) = {h0,h1};
                *reinterpret_cast<__nv_bfloat162*>(olo + (size_t)(row+8)*ldo + colg) = {l0,l1};
            }
        }
    } else { // EPI_LNRES
        __syncthreads();
        float* sf = reinterpret_cast<float*>(sm);
#pragma unroll
        for (int mt = 0; mt < 2; mt++){
            const int lr = wm*32 + mt*16 + (lane >> 2);
#pragma unroll
            for (int nt = 0; nt < 8; nt++){
                const int lc = wn*64 + nt*8 + ((lane & 3) << 1);
                const float b0 = bias[lc], b1 = bias[lc+1];
                sf[lr*132 + lc]       = acc[mt][nt][0] + b0;
                sf[lr*132 + lc + 1]   = acc[mt][nt][1] + b1;
                sf[(lr+8)*132 + lc]   = acc[mt][nt][2] + b0;
                sf[(lr+8)*132 + lc+1] = acc[mt][nt][3] + b1;
            }
        }
        __syncthreads();
        const float4 gg = reinterpret_cast<const float4*>(lng)[lane];
        const float4 lb = reinterpret_cast<const float4*>(lnb)[lane];
        for (int r = wid*16; r < wid*16 + 16; r++){
            float4 v = *reinterpret_cast<float4*>(sf + r*132 + lane*4);
            float mu = wredsum(v.x+v.y+v.z+v.w) * (1.0f/128.0f);
            float dx=v.x-mu, dy=v.y-mu, dz=v.z-mu, dw=v.w-mu;
            float var = wredsum(dx*dx+dy*dy+dz*dz+dw*dw) * (1.0f/128.0f);
            float rs = rsqrtf(var + 1e-5f);
            const int row = mBase + r;
            float* rp = res + (size_t)row*DIM;
            float4 r4 = reinterpret_cast<float4*>(rp)[lane];
            float o[4];
            o[0] = r4.x + dx*rs*gg.x + lb.x;
            o[1] = r4.y + dy*rs*gg.y + lb.y;
            o[2] = r4.z + dz*rs*gg.z + lb.z;
            o[3] = r4.w + dw*rs*gg.w + lb.w;
            float4 o4 = make_float4(o[0],o[1],o[2],o[3]);
            reinterpret_cast<float4*>(rp)[lane] = o4;
            if (writeFinal)
                reinterpret_cast<float4*>(fin + (size_t)row*DIM)[lane] = o4;
            float mu2 = wredsum(o[0]+o[1]+o[2]+o[3]) * (1.0f/128.0f);
            float e0=o[0]-mu2, e1=o[1]-mu2, e2=o[2]-mu2, e3=o[3]-mu2;
            float var2 = wredsum(e0*e0+e1*e1+e2*e2+e3*e3) * (1.0f/128.0f);
            float rs2 = rsqrtf(var2 + 1e-5f);
            float x2[4];
            x2[0] = e0*rs2*gg.x + lb.x; x2[1] = e1*rs2*gg.y + lb.y;
            x2[2] = e2*rs2*gg.z + lb.z; x2[3] = e3*rs2*gg.w + lb.w;
            split_store4(ohi + (size_t)row*DIM + lane*4,
                         olo + (size_t)row*DIM + lane*4, x2);
        }
    }
}

// ---------------- conv as implicit tensor-core GEMM (pipelined) --------------
__global__ void __launch_bounds__(256,2) conv_mma(
    const float* __restrict__ lng, const float* __restrict__ lnb)
{
    extern __shared__ char sm[];
    const uint32_t smb = smem_u32(sm);
    const int tid = threadIdx.x, wid = tid >> 5, lane = tid & 31;
    const int wm = wid & 3, wn = wid >> 2;
    const int mBase = blockIdx.x * 128;

    float acc[2][8][4];
#pragma unroll
    for (int mt = 0; mt < 2; mt++)
#pragma unroll
        for (int nt = 0; nt < 8; nt++)
#pragma unroll
            for (int i = 0; i < 4; i++) acc[mt][nt][i] = 0.f;

    const int lm  = tid >> 2;
    const int lc8 = (tid & 3) << 3;

    const int aRow = lane & 15, aKh = (lane >> 4) << 3;
    const int bRow = (lane & 7) + ((lane >> 4) << 3);
    const int bKh  = ((lane >> 3) & 1) << 3;

    auto issue_chunk = [&](int ch, int stage){
        char* st = sm + stage*STAGEB;
        const int tap = ch >> 2;
        const int kc  = (ch & 3) << 5;
        const int kh = tap/3 - 1, kw = tap%3 - 1;
#pragma unroll
        for (int i = 0; i < 2; i++){
            const int m = lm + i*64;
            const int p = mBase + m;
            const int b = p >> 12, hw = p & 4095;
            const int h = hw >> 6, w = hw & 63;
            const int hi = 2*h + kh, wi = 2*w + kw;
            const int so = (m*TS2 + lc8) << 1;
            if ((unsigned)hi < HI && (unsigned)wi < WI){
                size_t go = ((size_t)b*NPIX_IN + hi*WI + wi)*DIM + kc + lc8;
                cp16(st + OFF_AH + so, g_x_h + go);
                cp16(st + OFF_AL + so, g_x_l + go);
            } else {
                *reinterpret_cast<uint4*>(st + OFF_AH + so) = make_uint4(0,0,0,0);
                *reinterpret_cast<uint4*>(st + OFF_AL + so) = make_uint4(0,0,0,0);
            }
            size_t gb = (size_t)tap*DIM*DIM + (size_t)m*DIM + kc + lc8;
            cp16(st + OFF_BH + so, g_cw_h + gb);
            cp16(st + OFF_BL + so, g_cw_l + gb);
        }
        cp_commit();
    };

    issue_chunk(0, 0);
    issue_chunk(1, 1);

    for (int c = 0; c < 36; c++){
        if (c + 1 < 36) cp_wait<1>(); else cp_wait<0>();
        __syncthreads();
        const uint32_t stb = smb + (uint32_t)((c & 1)*STAGEB);
#pragma unroll
        for (int ks = 0; ks < 2; ks++){
            uint32_t ah[2][4], al[2][4];
#pragma unroll
            for (int mt = 0; mt < 2; mt++){
                const int eoff = ((wm*32 + mt*16 + aRow)*TS2 + ks*16 + aKh) << 1;
                ldsm_x4(ah[mt], stb + OFF_AH + eoff);
                ldsm_x4(al[mt], stb + OFF_AL + eoff);
            }
#pragma unroll
            for (int np = 0; np < 4; np++){
                const int eoff = ((wn*64 + np*16 + bRow)*TS2 + ks*16 + bKh) << 1;
                uint32_t bh4[4], bl4[4];
                ldsm_x4(bh4, stb + OFF_BH + eoff);
                ldsm_x4(bl4, stb + OFF_BL + eoff);
#pragma unroll
                for (int mt = 0; mt < 2; mt++){
#pragma unroll
                    for (int hf = 0; hf < 2; hf++){
                        float* cc = acc[mt][np*2 + hf];
                        mma16816(cc, ah[mt], bh4[hf*2], bh4[hf*2+1]);
                        mma16816(cc, al[mt], bh4[hf*2], bh4[hf*2+1]);
                        mma16816(cc, ah[mt], bl4[hf*2], bl4[hf*2+1]);
                    }
                }
            }
        }
        __syncthreads();
        if (c + 2 < 36) issue_chunk(c + 2, c & 1);
    }

    __syncthreads();
    float* sf = reinterpret_cast<float*>(sm);
#pragma unroll
    for (int mt = 0; mt < 2; mt++){
        const int lr = wm*32 + mt*16 + (lane >> 2);
#pragma unroll
        for (int nt = 0; nt < 8; nt++){
            const int lc = wn*64 + nt*8 + ((lane & 3) << 1);
            sf[lr*132 + lc]       = acc[mt][nt][0];
            sf[lr*132 + lc + 1]   = acc[mt][nt][1];
            sf[(lr+8)*132 + lc]   = acc[mt][nt][2];
            sf[(lr+8)*132 + lc+1] = acc[mt][nt][3];
        }
    }
    __syncthreads();
    const float4 gg = reinterpret_cast<const float4*>(lng)[lane];
    const float4 lb = reinterpret_cast<const float4*>(lnb)[lane];
    for (int r = wid*16; r < wid*16 + 16; r++){
        float4 v = *reinterpret_cast<float4*>(sf + r*132 + lane*4);
        float mu = wredsum(v.x+v.y+v.z+v.w) * (1.0f/128.0f);
        float dx=v.x-mu, dy=v.y-mu, dz=v.z-mu, dw=v.w-mu;
        float var = wredsum(dx*dx+dy*dy+dz*dz+dw*dw) * (1.0f/128.0f);
        float rs = rsqrtf(var + 1e-5f);
        const int row = mBase + r;
        float o[4];
        o[0] = dx*rs*gg.x + lb.x; o[1] = dy*rs*gg.y + lb.y;
        o[2] = dz*rs*gg.z + lb.z; o[3] = dw*rs*gg.w + lb.w;
        reinterpret_cast<float4*>(g_xout + (size_t)row*DIM)[lane] =
            make_float4(o[0],o[1],o[2],o[3]);
        float mu2 = wredsum(o[0]+o[1]+o[2]+o[3]) * (1.0f/128.0f);
        float e0=o[0]-mu2, e1=o[1]-mu2, e2=o[2]-mu2, e3=o[3]-mu2;
        float var2 = wredsum(e0*e0+e1*e1+e2*e2+e3*e3) * (1.0f/128.0f);
        float rs2 = rsqrtf(var2 + 1e-5f);
        float x2[4];
        x2[0] = e0*rs2*gg.x + lb.x; x2[1] = e1*rs2*gg.y + lb.y;
        x2[2] = e2*rs2*gg.z + lb.z; x2[3] = e3*rs2*gg.w + lb.w;
        split_store4(g_xq_h + (size_t)row*DIM + lane*4,
                     g_xq_l + (size_t)row*DIM + lane*4, x2);
    }
}

// ---------------- unified preprocessing kernel -------------------------------
#define PREP_ROW_BLOCKS (NROWS_IN/8)    // 8192
__global__ void __launch_bounds__(256) prep_kernel(
    const float* __restrict__ x,
    const float* __restrict__ convw,
    const float* __restrict__ q_w, const float* __restrict__ k_w,
    const float* __restrict__ v_w,
    const float* __restrict__ w1, const float* __restrict__ w2,
    const float* __restrict__ lin_g, const float* __restrict__ lin_b)
{
    if (blockIdx.x < PREP_ROW_BLOCKS){
        const int lane = threadIdx.x & 31, warp = threadIdx.x >> 5;
        const size_t row = (size_t)blockIdx.x*8 + warp;
        float4 v = reinterpret_cast<const float4*>(x + row*DIM)[lane];
        float t[4] = {v.x, v.y, v.z, v.w};
        split_store4(g_x_h + row*DIM + lane*4, g_x_l + row*DIM + lane*4, t);
        float mu = wredsum(v.x+v.y+v.z+v.w) * (1.0f/DIM);
        float dx=v.x-mu, dy=v.y-mu, dz=v.z-mu, dw=v.w-mu;
        float var = wredsum(dx*dx+dy*dy+dz*dz+dw*dw) * (1.0f/DIM);
        float rs = rsqrtf(var + 1e-5f);
        float4 gg = reinterpret_cast<const float4*>(lin_g)[lane];
        float4 bb = reinterpret_cast<const float4*>(lin_b)[lane];
        float u[4];
        u[0] = dx*rs*gg.x + bb.x; u[1] = dy*rs*gg.y + bb.y;
        u[2] = dz*rs*gg.z + bb.z; u[3] = dw*rs*gg.w + bb.w;
        split_store4(g_xli_h + row*DIM + lane*4, g_xli_l + row*DIM + lane*4, u);
        return;
    }
    int idx = (blockIdx.x - PREP_ROW_BLOCKS)*256 + threadIdx.x;  // [0, 262144)
    __nv_bfloat16 h, l;
    if (idx < 16384){                       // q_w [128,128] -> [N,K]
        int k = idx >> 7, n = idx & 127;
        split2(q_w[idx], h, l);
        g_wq_h[n*DIM + k] = h; g_wq_l[n*DIM + k] = l;
    } else if (idx < 32768){                // k_w
        int i = idx - 16384;
        int k = i >> 7, n = i & 127;
        split2(k_w[i], h, l);
        g_wk_h[n*DIM + k] = h; g_wk_l[n*DIM + k] = l;
    } else if (idx < 49152){                // v_w
        int i = idx - 32768;
        int k = i >> 7, n = i & 127;
        split2(v_w[i], h, l);
        g_wv_h[n*DIM + k] = h; g_wv_l[n*DIM + k] = l;
    } else if (idx < 81920){                // w1 [128,256] -> [256,128]
        int i = idx - 49152;
        int k = i >> 8, n = i & 255;
        split2(w1[i], h, l);
        g_w1_h[(size_t)n*DIM + k] = h; g_w1_l[(size_t)n*DIM + k] = l;
    } else if (idx < 114688){               // w2 [256,128] -> [128,256]
        int i = idx - 81920;
        int k = i >> 7, n = i & 127;
        split2(w2[i], h, l);
        g_w2_h[(size_t)n*256 + k] = h; g_w2_l[(size_t)n*256 + k] = l;
    } else {                                // convw [o][i][tap] -> [tap][o][i]
        int i = idx - 114688;               // [0, 147456)
        int o   = i / (DIM*9);
        int rem = i - o*(DIM*9);
        int ii  = rem / 9;
        int tap = rem - ii*9;
        split2(convw[i], h, l);
        g_cw_h[(size_t)tap*DIM*DIM + o*DIM + ii] = h;
        g_cw_l[(size_t)tap*DIM*DIM + o*DIM + ii] = l;
    }
}

// ---------------- attention: scores + softmax + eps + colsum atomics ---------
__global__ void attn_kernel(const float* __restrict__ rpb,
                            const float* __restrict__ tau,
                            float* __restrict__ attn_out)
{
    const int tid = threadIdx.x, warp = tid >> 5, lane = tid & 31;
    const int id  = blockIdx.x*4 + warp;
    const int b   = id >> 14;
    const int rem = id & 16383;
    const int g   = rem >> 12;
    const int hw  = rem & 4095;
    const int h = hw >> 6, w = hw & 63;
    const int ga = g >> 1, gb = g & 1;
    const int pix = (2*h + ga)*WI + 2*w + gb;
    const float4 kv = reinterpret_cast<const float4*>(g_k + ((size_t)b*NPIX_IN + pix)*DIM)[lane];
    const float scale = expf(tau[0]);
    const int ch = min(max(h,1), HO-2), cw = min(max(w,1), WO-2);

    float p[9];
    float m = -1e30f;
#pragma unroll
    for (int t = 0; t < 9; t++){
        const int nh = ch + t/3 - 1, nw = cw + t%3 - 1;
        const float4 q4 = reinterpret_cast<const float4*>(g_q + ((size_t)b*NPIX_OUT + nh*WO + nw)*DIM)[lane];
        float d = kv.x*q4.x + kv.y*q4.y + kv.z*q4.z + kv.w*q4.w;
        d = wredsum(d);
        const float val = (d + rpb[g*9 + t]) * scale;
        p[t] = val;
        m = fmaxf(m, val);
    }
    float s = 0.f;
#pragma unroll
    for (int t = 0; t < 9; t++){ p[t] = expf(p[t] - m); s += p[t]; }
    const float inv = 1.f/s;
#pragma unroll
    for (int t = 0; t < 9; t++) p[t] = p[t]*inv + 1e-6f;

    if (lane == 0){
        float* ao = attn_out + (size_t)id*9;
#pragma unroll
        for (int t = 0; t < 9; t++) ao[t] = p[t];
#pragma unroll
        for (int t = 0; t < 9; t++){
            const int nh = ch + t/3 - 1, nw = cw + t%3 - 1;
            atomicAdd(&g_colsum[b*NPIX_OUT + nh*WO + nw], p[t]);
        }
    }
}

// ---------------- aggregation: A_col + upd + residual + xout split -----------
__global__ void upd_kernel(const float* __restrict__ attn_in,
                           float* __restrict__ acol_out)
{
    const int tid = threadIdx.x, warp = tid >> 5, lane = tid & 31;
    const int id = blockIdx.x*4 + warp;
    const int b  = id >> 12;
    const int hw = id & 4095;
    const int h = hw >> 6, w = hw & 63;
    const int ch = min(max(h,1), HO-2), cw = min(max(w,1), WO-2);

    float inv_dn[9];
#pragma unroll
    for (int t = 0; t < 9; t++){
        const int nh = ch + t/3 - 1, nw = cw + t%3 - 1;
        inv_dn[t] = 1.0f / (g_colsum[b*NPIX_OUT + nh*WO + nw] + 1e-8f);
    }
    float4 acc = make_float4(0.f,0.f,0.f,0.f);
#pragma unroll
    for (int g = 0; g < 4; g++){
        const int ga = g >> 1, gb = g & 1;
        const size_t base = ((size_t)((b*4 + g)*NPIX_OUT) + hw)*9;
        const float* ab = attn_in + base;
        float* cb = acol_out + base;
#pragma unroll
        for (int t = 0; t < 9; t++){
            const float coeff = ab[t] * inv_dn[t];
            if (lane == 0) cb[t] = coeff;
            const int nh = ch + t/3 - 1, nw = cw + t%3 - 1;
            const int pix = (2*nh + ga)*WI + 2*nw + gb;
            const float4 vv = reinterpret_cast<const float4*>(g_v + ((size_t)b*NPIX_IN + pix)*DIM)[lane];
            acc.x += coeff*vv.x; acc.y += coeff*vv.y; acc.z += coeff*vv.z; acc.w += coeff*vv.w;
        }
    }
    float4* xo = reinterpret_cast<float4*>(g_xout + (size_t)id*DIM);
    float4 v = xo[lane];
    v.x += acc.x; v.y += acc.y; v.z += acc.z; v.w += acc.w;
    xo[lane] = v;
    float t4[4] = {v.x, v.y, v.z, v.w};
    split_store4(g_xo_h + (size_t)id*DIM + lane*4,
                 g_xo_l + (size_t)id*DIM + lane*4, t4);
}

// ---------------- launch ------------------------------------------------------
extern "C" void kernel_launch(void* const* d_in, const int* in_sizes, int n_in,
                              void* d_out, int out_size)
{
    const float* x      = (const float*)d_in[0];
    const float* convw  = (const float*)d_in[1];
    const float* q_w    = (const float*)d_in[2];
    const float* k_w    = (const float*)d_in[3];
    const float* v_w    = (const float*)d_in[4];
    const float* w1     = (const float*)d_in[5];
    const float* b1     = (const float*)d_in[6];
    const float* w2     = (const float*)d_in[7];
    const float* b2     = (const float*)d_in[8];
    const float* lin_g  = (const float*)d_in[9];
    const float* lin_b  = (const float*)d_in[10];
    const float* lout_g = (const float*)d_in[11];
    const float* lout_b = (const float*)d_in[12];
    const float* tau    = (const float*)d_in[13];
    const float* rpb    = (const float*)d_in[14];

    float* out      = (float*)d_out;
    float* out_x    = out;
    float* out_attn = out + (size_t)NROWS_OUT*DIM;
    float* out_acol = out_attn + (size_t)BATCH*4*NPIX_OUT*9;

    float *pk, *pv, *pq, *pxout, *pcs;
    cudaGetSymbolAddress((void**)&pk,    g_k);
    cudaGetSymbolAddress((void**)&pv,    g_v);
    cudaGetSymbolAddress((void**)&pq,    g_q);
    cudaGetSymbolAddress((void**)&pxout, g_xout);
    cudaGetSymbolAddress((void**)&pcs,   g_colsum);
    __nv_bfloat16 *pxh,*pxl,*plih,*plil,*poh,*pol,*pqh,*pql,*phh,*phl;
    __nv_bfloat16 *wqh,*wql,*wkh,*wkl,*wvh,*wvl,*w1h,*w1l,*w2h,*w2l;
    cudaGetSymbolAddress((void**)&pxh,  g_x_h);   cudaGetSymbolAddress((void**)&pxl,  g_x_l);
    cudaGetSymbolAddress((void**)&plih, g_xli_h); cudaGetSymbolAddress((void**)&plil, g_xli_l);
    cudaGetSymbolAddress((void**)&poh,  g_xo_h);  cudaGetSymbolAddress((void**)&pol,  g_xo_l);
    cudaGetSymbolAddress((void**)&pqh,  g_xq_h);  cudaGetSymbolAddress((void**)&pql,  g_xq_l);
    cudaGetSymbolAddress((void**)&phh,  g_hh_h);  cudaGetSymbolAddress((void**)&phl,  g_hh_l);
    cudaGetSymbolAddress((void**)&wqh,  g_wq_h);  cudaGetSymbolAddress((void**)&wql,  g_wq_l);
    cudaGetSymbolAddress((void**)&wkh,  g_wk_h);  cudaGetSymbolAddress((void**)&wkl,  g_wk_l);
    cudaGetSymbolAddress((void**)&wvh,  g_wv_h);  cudaGetSymbolAddress((void**)&wvl,  g_wv_l);
    cudaGetSymbolAddress((void**)&w1h,  g_w1_h);  cudaGetSymbolAddress((void**)&w1l,  g_w1_l);
    cudaGetSymbolAddress((void**)&w2h,  g_w2_h);  cudaGetSymbolAddress((void**)&w2l,  g_w2_l);

    cudaFuncSetAttribute(gemm_mma, cudaFuncAttributeMaxDynamicSharedMemorySize, SMEM_MMA);
    cudaFuncSetAttribute(conv_mma, cudaFuncAttributeMaxDynamicSharedMemorySize, SMEM_MMA);

    // ---- preprocessing: single kernel (row splits + all weight splits) ----
    prep_kernel<<<PREP_ROW_BLOCKS + 1024, 256>>>(
        x, convw, q_w, k_w, v_w, w1, w2, lin_g, lin_b);

    // k = LN_in(x) @ k_w  AND  v = x @ v_w  in one launch (z = 0 / 1)
    gemm_mma<<<dim3(NROWS_IN/128, 1, 2), 256, SMEM_MMA>>>(
        plih, plil, 128, wkh, wkl,
        nullptr, nullptr, nullptr, pk, 128, nullptr, nullptr, nullptr, nullptr, 0,
        nullptr, pxh, pxl, wvh, wvl, pv,
        EPI_STORE, 0);
    conv_mma<<<NROWS_OUT/128, 256, SMEM_MMA>>>(lout_g, lout_b);

    for (int it = 0; it < 3; it++){
        // q = LN(x_out) @ q_w   (also zeroes colsum for the attn that follows)
        gemm_mma<<<NROWS_OUT/128, 256, SMEM_MMA>>>(pqh, pql, 128, wqh, wql,
            nullptr, nullptr, nullptr, pq, 128, nullptr, nullptr, nullptr, nullptr, 0,
            pcs, nullptr, nullptr, nullptr, nullptr, nullptr,
            EPI_STORE, 0);
        attn_kernel<<<(BATCH*4*NPIX_OUT)/4, 128>>>(rpb, tau, out_attn);
        upd_kernel<<<NROWS_OUT/4, 128>>>(out_attn, out_acol);
        // h = gelu(x_out @ w1 + b1) -> bf16 split
        gemm_mma<<<dim3(NROWS_OUT/128, 2), 256, SMEM_MMA>>>(poh, pol, 128, w1h, w1l,
            b1, nullptr, nullptr, nullptr, 0, nullptr, nullptr, phh, phl, 256,
            nullptr, nullptr, nullptr, nullptr, nullptr, nullptr,
            EPI_GELU, 0);
        // x_out += LN(h @ w2 + b2); xq = LN(x_out) split
        gemm_mma<<<NROWS_OUT/128, 256, SMEM_MMA>>>(phh, phl, 256, w2h, w2l,
            b2, lout_g, lout_b, nullptr, 0, pxout, out_x, pqh, pql, 128,
            nullptr, nullptr, nullptr, nullptr, nullptr, nullptr,
            EPI_LNRES, it == 2 ? 1 : 0);
    }
    (void)in_sizes; (void)n_in; (void)out_size;
}